// round 13
// baseline (speedup 1.0000x reference)
#include <cuda_runtime.h>
#include <cuda_bf16.h>
#include <cstdint>

// Problem constants
#define PIX 16384        // B*H*W
#define NSEQ 4096        // H*W
#define BSZ 4
#define CH 128
#define THITA 1e-4f

typedef __nv_bfloat16 bf16;

// ---------------- scratch (device globals; no allocation allowed) -------------
__device__ float g_nowval[PIX * 128];
__device__ bf16 g_qb[PIX * 128];
__device__ bf16 g_kb[PIX * 128];
__device__ bf16 g_vb[PIX * 128];
// bf16 weights
__device__ bf16 g_wb1[256 * 128];   // [w_pro_key ; w_lat_key]
__device__ bf16 g_wb2[256 * 128];   // [w_pro_val ; w_lat_val]
__device__ bf16 g_wbt[128 * 256];   // w_tmp1
__device__ bf16 g_wbnk[128 * 128];  // w_now_key
__device__ bf16 g_wbq[128 * 128];
__device__ bf16 g_wbk[128 * 128];
__device__ bf16 g_wbv[128 * 128];
__device__ bf16 g_w8hi[128 * 128];  // w_now_val split hi
__device__ bf16 g_w8lo[128 * 128];  // w_now_val split lo
__device__ float g_bc1[256];
__device__ float g_bc2[256];

// ---------------- weight prep ---------------------------------------------------
__global__ void __launch_bounds__(256) prep_w_kernel(
    const float* __restrict__ wpk, const float* __restrict__ wlk,
    const float* __restrict__ wpv, const float* __restrict__ wlv,
    const float* __restrict__ wt,  const float* __restrict__ wnk,
    const float* __restrict__ wq,  const float* __restrict__ wk,
    const float* __restrict__ wv,  const float* __restrict__ wnv,
    const float* __restrict__ bpk, const float* __restrict__ blk,
    const float* __restrict__ bpv, const float* __restrict__ blv) {
    int i = blockIdx.x * blockDim.x + threadIdx.x;   // 0..163839
    if (i < 32768) {
        g_wb1[i] = __float2bfloat16(i < 16384 ? wpk[i] : wlk[i - 16384]);
        g_wb2[i] = __float2bfloat16(i < 16384 ? wpv[i] : wlv[i - 16384]);
        g_wbt[i] = __float2bfloat16(wt[i]);
    } else if (i < 49152) {
        int j = i - 32768;
        if (j < 16384) {
            g_wbnk[j] = __float2bfloat16(wnk[j]);
            float v = wnv[j];
            bf16 h = __float2bfloat16(v);
            g_w8hi[j] = h;
            g_w8lo[j] = __float2bfloat16(v - __bfloat162float(h));
        }
    } else if (i < 65536) {
        int j = i - 49152;
        g_wbq[j] = __float2bfloat16(wq[j]);
        g_wbk[j] = __float2bfloat16(wk[j]);
        g_wbv[j] = __float2bfloat16(wv[j]);
    }
    if (i < 256) {
        g_bc1[i] = i < 128 ? bpk[i] : blk[i - 128];
        g_bc2[i] = i < 128 ? bpv[i] : blv[i - 128];
    }
}

// ---------------- mma / ldmatrix helpers --------------------------------------
__device__ __forceinline__ void mma16816(float* c, const uint32_t* a, const uint32_t* b) {
    asm volatile(
        "mma.sync.aligned.m16n8k16.row.col.f32.bf16.bf16.f32 "
        "{%0,%1,%2,%3}, {%4,%5,%6,%7}, {%8,%9}, {%0,%1,%2,%3};"
        : "+f"(c[0]), "+f"(c[1]), "+f"(c[2]), "+f"(c[3])
        : "r"(a[0]), "r"(a[1]), "r"(a[2]), "r"(a[3]), "r"(b[0]), "r"(b[1]));
}

__device__ __forceinline__ void ldsm4(uint32_t& r0, uint32_t& r1, uint32_t& r2, uint32_t& r3,
                                      const void* p) {
    uint32_t addr = (uint32_t)__cvta_generic_to_shared(p);
    asm volatile("ldmatrix.sync.aligned.m8n8.x4.shared.b16 {%0,%1,%2,%3}, [%4];"
                 : "=r"(r0), "=r"(r1), "=r"(r2), "=r"(r3) : "r"(addr));
}

__device__ __forceinline__ void ldsm4t(uint32_t& r0, uint32_t& r1, uint32_t& r2, uint32_t& r3,
                                       const void* p) {
    uint32_t addr = (uint32_t)__cvta_generic_to_shared(p);
    asm volatile("ldmatrix.sync.aligned.m8n8.x4.trans.shared.b16 {%0,%1,%2,%3}, [%4];"
                 : "=r"(r0), "=r"(r1), "=r"(r2), "=r"(r3) : "r"(addr));
}

__device__ __forceinline__ uint32_t packbf2(float lo, float hi) {
    uint32_t d;
    asm("cvt.rn.bf16x2.f32 %0, %1, %2;" : "=r"(d) : "f"(hi), "f"(lo));
    return d;
}

__device__ __forceinline__ void cpasync16(void* dst, const void* src) {
    uint32_t d = (uint32_t)__cvta_generic_to_shared(dst);
    asm volatile("cp.async.cg.shared.global [%0], [%1], 16;" :: "r"(d), "l"(src));
}
#define CP_COMMIT() asm volatile("cp.async.commit_group;")
#define CP_WAIT0()  asm volatile("cp.async.wait_group 0;")
#define CP_WAIT1()  asm volatile("cp.async.wait_group 1;")

// ============ fused conv chain (unchanged, validated) ==========================
template <int K>
__device__ __forceinline__ void stage_gemm(
    const bf16* __restrict__ inb,
    const bf16* __restrict__ wg,
    const float* __restrict__ bias,
    bf16* __restrict__ wbuf,
    bf16* __restrict__ outb,
    bf16* __restrict__ outg,
    int m0, int tid) {
    const int lane = tid & 31, wid = tid >> 5;
    const int wm = (wid & 1) * 64, wn = (wid >> 1) * 32;
    const int g = lane >> 2, tc = lane & 3;
    const int rA_loc = ((lane >> 3) & 1) * 8 + (lane & 7);
    const int cA_bit = (lane >> 4) & 1;
    const int rB_loc = ((lane >> 4) & 1) * 8 + (lane & 7);
    const int cB_bit = (lane >> 3) & 1;
    constexpr int CPR = K >> 3;

#pragma unroll
    for (int i = tid; i < 128 * CPR; i += 256) {
        int n = i / CPR, ck = i % CPR;
        int kb = ck >> 3, c8 = ck & 7;
        cpasync16((uint4*)wbuf + kb * 1024 + n * 8 + (c8 ^ (n & 7)),
                  (const uint4*)wg + i);
    }
    CP_COMMIT();
    CP_WAIT0();
    __syncthreads();

    float acc[4][4][4];
#pragma unroll
    for (int i = 0; i < 4; i++)
#pragma unroll
        for (int j = 0; j < 4; j++)
#pragma unroll
            for (int l = 0; l < 4; l++) acc[i][j][l] = 0.f;

#pragma unroll
    for (int kb = 0; kb < K / 64; kb++) {
        const bf16* As = inb + kb * 8192;
        const bf16* Bs = wbuf + kb * 8192;
#pragma unroll
        for (int ks = 0; ks < 4; ks++) {
            uint32_t a[4][4], bf[2][4];
#pragma unroll
            for (int mi = 0; mi < 4; mi++) {
                int r = wm + mi * 16 + rA_loc;
                int ch = 2 * ks + cA_bit;
                ldsm4(a[mi][0], a[mi][1], a[mi][2], a[mi][3],
                      As + r * 64 + ((ch ^ (r & 7)) << 3));
            }
#pragma unroll
            for (int ni = 0; ni < 2; ni++) {
                int r = wn + ni * 16 + rB_loc;
                int ch = 2 * ks + cB_bit;
                ldsm4(bf[ni][0], bf[ni][1], bf[ni][2], bf[ni][3],
                      Bs + r * 64 + ((ch ^ (r & 7)) << 3));
            }
#pragma unroll
            for (int mi = 0; mi < 4; mi++)
#pragma unroll
                for (int ni = 0; ni < 2; ni++) {
                    uint32_t b0[2] = {bf[ni][0], bf[ni][1]};
                    mma16816(acc[mi][2 * ni], a[mi], b0);
                    uint32_t b1[2] = {bf[ni][2], bf[ni][3]};
                    mma16816(acc[mi][2 * ni + 1], a[mi], b1);
                }
        }
    }

#pragma unroll
    for (int mi = 0; mi < 4; mi++) {
        int r0 = wm + mi * 16 + g;
#pragma unroll
        for (int n8 = 0; n8 < 4; n8++) {
            int c = wn + n8 * 8 + 2 * tc;
            float2 bv = *(const float2*)(bias + c);
            uint32_t p0 = packbf2(fmaxf(acc[mi][n8][0] + bv.x, 0.f),
                                  fmaxf(acc[mi][n8][1] + bv.y, 0.f));
            uint32_t p1 = packbf2(fmaxf(acc[mi][n8][2] + bv.x, 0.f),
                                  fmaxf(acc[mi][n8][3] + bv.y, 0.f));
            if (outb) {
                int kb_o = c >> 6, cl = c & 63, chk = cl >> 3, off = cl & 7;
                bf16* base = outb + kb_o * 8192;
                *(uint32_t*)(base + r0 * 64 + ((chk ^ (r0 & 7)) << 3) + off) = p0;
                int r1 = r0 + 8;
                *(uint32_t*)(base + r1 * 64 + ((chk ^ (r1 & 7)) << 3) + off) = p1;
            } else {
                *(uint32_t*)(outg + (size_t)(m0 + r0) * 128 + c) = p0;
                *(uint32_t*)(outg + (size_t)(m0 + r0 + 8) * 128 + c) = p1;
            }
        }
    }
    __syncthreads();
}

#define FUSED_SMEM (65536 + 65536 + 32768 + 65536)   // A,B,C,W = 229376 B

__global__ void __launch_bounds__(256, 1) fused_conv_kernel(
    const float* __restrict__ event,
    const float* __restrict__ w0, const float* __restrict__ b0,
    const float* __restrict__ w6, const float* __restrict__ b6,
    const bf16* __restrict__ wb1, const float* __restrict__ bc1,
    const bf16* __restrict__ wb2, const float* __restrict__ bc2,
    const bf16* __restrict__ wbt, const float* __restrict__ bt,
    const bf16* __restrict__ wbnk, const float* __restrict__ bnk,
    const bf16* __restrict__ wbq, const float* __restrict__ bq,
    const bf16* __restrict__ wbk, const float* __restrict__ bk,
    const bf16* __restrict__ wbv, const float* __restrict__ bv,
    bf16* __restrict__ qb, bf16* __restrict__ kb_, bf16* __restrict__ vb) {
    extern __shared__ char sm[];
    bf16* A = (bf16*)sm;
    bf16* B = (bf16*)(sm + 65536);
    bf16* C = (bf16*)(sm + 131072);
    bf16* W = (bf16*)(sm + 163840);
    const int tid = threadIdx.x;
    const int m0 = blockIdx.x * 128;
    const float* ev = event + (size_t)(m0 >> 12) * 6 * NSEQ + (m0 & 4095);

    for (int i = tid; i < 4096; i += 256) {
        int r = i >> 5, ck = i & 31;
        float x0 = ev[r], x1 = ev[NSEQ + r], x2 = ev[4 * NSEQ + r], x3 = ev[5 * NSEQ + r];
        uint32_t pk[4];
#pragma unroll
        for (int j = 0; j < 4; j++) {
            int c0 = ck * 8 + 2 * j, c1 = c0 + 1;
            float v0 = fmaf(w0[c0 * 4 + 3], x3, fmaf(w0[c0 * 4 + 2], x2,
                       fmaf(w0[c0 * 4 + 1], x1, fmaf(w0[c0 * 4], x0, b0[c0]))));
            float v1 = fmaf(w0[c1 * 4 + 3], x3, fmaf(w0[c1 * 4 + 2], x2,
                       fmaf(w0[c1 * 4 + 1], x1, fmaf(w0[c1 * 4], x0, b0[c1]))));
            pk[j] = packbf2(fmaxf(v0, 0.f), fmaxf(v1, 0.f));
        }
        ((uint4*)A)[(ck >> 3) * 1024 + r * 8 + ((ck & 7) ^ (r & 7))] =
            make_uint4(pk[0], pk[1], pk[2], pk[3]);
    }
    __syncthreads();

    stage_gemm<128>(A, wb1, bc1, W, B, nullptr, m0, tid);
    stage_gemm<128>(A, wb1 + 128 * 128, bc1 + 128, W, B + 2 * 8192, nullptr, m0, tid);
    stage_gemm<256>(B, wbt, bt, W, C, nullptr, m0, tid);
    stage_gemm<128>(C, wbq, bq, W, nullptr, qb, m0, tid);

    stage_gemm<128>(A + 2 * 8192, wb2, bc2, W, B, nullptr, m0, tid);
    stage_gemm<128>(A + 2 * 8192, wb2 + 128 * 128, bc2 + 128, W, B + 2 * 8192, nullptr, m0, tid);
    stage_gemm<256>(B, wbt, bt, W, C, nullptr, m0, tid);
    stage_gemm<128>(C, wbv, bv, W, nullptr, vb, m0, tid);

    for (int i = tid; i < 2048; i += 256) {
        int r = i >> 4, ck = i & 15;
        float x = ev[2 * NSEQ + r], y = ev[3 * NSEQ + r];
        uint32_t pk[4];
#pragma unroll
        for (int j = 0; j < 4; j++) {
            int c0 = ck * 8 + 2 * j, c1 = c0 + 1;
            float v0 = fmaxf(fmaf(w6[c0 * 2 + 1], y, fmaf(w6[c0 * 2], x, b6[c0])), 0.f);
            float v1 = fmaxf(fmaf(w6[c1 * 2 + 1], y, fmaf(w6[c1 * 2], x, b6[c1])), 0.f);
            pk[j] = packbf2(v0, v1);
        }
        ((uint4*)A)[(ck >> 3) * 1024 + r * 8 + ((ck & 7) ^ (r & 7))] =
            make_uint4(pk[0], pk[1], pk[2], pk[3]);
    }
    __syncthreads();
    stage_gemm<128>(A, wbnk, bnk, W, C, nullptr, m0, tid);
    stage_gemm<128>(C, wbk, bk, W, nullptr, kb_, m0, tid);
}

// ---------------- now_val: fused nowf + split-bf16 GEMM (unchanged) -----------
#define NV_SMEM (65536 + 1024 + 1024 + 512)

__global__ void __launch_bounds__(256) gemm_nowval(
    const float* __restrict__ event,
    const float* __restrict__ w6, const float* __restrict__ b6,
    const bf16* __restrict__ w8hi, const bf16* __restrict__ w8lo,
    const float* __restrict__ b8,
    float* __restrict__ out) {
    extern __shared__ char sm[];
    bf16* Ah = (bf16*)sm;
    bf16* Al = Ah + 128 * 64;
    bf16* Bh = Al + 128 * 64;
    bf16* Bl = Bh + 128 * 64;
    float* x2s = (float*)(sm + 65536);
    float* w6s = x2s + 256;
    float* b6s = w6s + 256;

    const int tid = threadIdx.x, lane = tid & 31, wid = tid >> 5;
    const int m0 = blockIdx.x * 128;
    const int wm = (wid & 1) * 64, wn = (wid >> 1) * 32;
    const int g = lane >> 2, tc = lane & 3;
    const int rA_loc = ((lane >> 3) & 1) * 8 + (lane & 7);
    const int cA_bit = (lane >> 4) & 1;
    const int rB_loc = ((lane >> 4) & 1) * 8 + (lane & 7);
    const int cB_bit = (lane >> 3) & 1;

    {
        int bb = m0 >> 12;
        const float* e = event + (size_t)bb * 6 * NSEQ + (m0 & 4095);
        if (tid < 128) {
            x2s[2 * tid] = e[2 * NSEQ + tid];
            x2s[2 * tid + 1] = e[3 * NSEQ + tid];
            b6s[tid] = b6[tid];
        } else {
            int j = tid - 128;
            ((float2*)w6s)[j] = ((const float2*)w6)[j];
        }
    }
    __syncthreads();

    float acc[4][4][4];
#pragma unroll
    for (int i = 0; i < 4; i++)
#pragma unroll
        for (int j = 0; j < 4; j++)
#pragma unroll
            for (int l = 0; l < 4; l++) acc[i][j][l] = 0.f;

    for (int k0 = 0; k0 < 128; k0 += 64) {
#pragma unroll
        for (int i = 0; i < 4; i++) {
            int li = tid + i * 256;
            int r = li >> 3, cch = li & 7;
            float x0 = x2s[2 * r], x1 = x2s[2 * r + 1];
            uint4 hq, lq;
            bf16* hp = (bf16*)&hq;
            bf16* lp = (bf16*)&lq;
#pragma unroll
            for (int j = 0; j < 8; j++) {
                int k = k0 + cch * 8 + j;
                float v = fmaxf(fmaf(w6s[2 * k + 1], x1, fmaf(w6s[2 * k], x0, b6s[k])), 0.f);
                bf16 h = __float2bfloat16(v);
                hp[j] = h;
                lp[j] = __float2bfloat16(v - __bfloat162float(h));
            }
            int sidx = r * 8 + (cch ^ (r & 7));
            ((uint4*)Ah)[sidx] = hq;
            ((uint4*)Al)[sidx] = lq;
            ((uint4*)Bh)[sidx] = *(const uint4*)(w8hi + (size_t)r * 128 + k0 + cch * 8);
            ((uint4*)Bl)[sidx] = *(const uint4*)(w8lo + (size_t)r * 128 + k0 + cch * 8);
        }
        __syncthreads();
#pragma unroll
        for (int ks = 0; ks < 4; ks++) {
            uint32_t ah[4][4], al[4][4], bh[2][4], bl[2][4];
#pragma unroll
            for (int mi = 0; mi < 4; mi++) {
                int r = wm + mi * 16 + rA_loc;
                int ch = 2 * ks + cA_bit;
                int off = r * 64 + ((ch ^ (r & 7)) << 3);
                ldsm4(ah[mi][0], ah[mi][1], ah[mi][2], ah[mi][3], Ah + off);
                ldsm4(al[mi][0], al[mi][1], al[mi][2], al[mi][3], Al + off);
            }
#pragma unroll
            for (int ni = 0; ni < 2; ni++) {
                int r = wn + ni * 16 + rB_loc;
                int ch = 2 * ks + cB_bit;
                int off = r * 64 + ((ch ^ (r & 7)) << 3);
                ldsm4(bh[ni][0], bh[ni][1], bh[ni][2], bh[ni][3], Bh + off);
                ldsm4(bl[ni][0], bl[ni][1], bl[ni][2], bl[ni][3], Bl + off);
            }
#pragma unroll
            for (int mi = 0; mi < 4; mi++)
#pragma unroll
                for (int ni = 0; ni < 2; ni++) {
                    uint32_t h0[2] = {bh[ni][0], bh[ni][1]};
                    uint32_t h1[2] = {bh[ni][2], bh[ni][3]};
                    uint32_t l0[2] = {bl[ni][0], bl[ni][1]};
                    uint32_t l1[2] = {bl[ni][2], bl[ni][3]};
                    mma16816(acc[mi][2 * ni], ah[mi], h0);
                    mma16816(acc[mi][2 * ni + 1], ah[mi], h1);
                    mma16816(acc[mi][2 * ni], ah[mi], l0);
                    mma16816(acc[mi][2 * ni + 1], ah[mi], l1);
                    mma16816(acc[mi][2 * ni], al[mi], h0);
                    mma16816(acc[mi][2 * ni + 1], al[mi], h1);
                }
        }
        __syncthreads();
    }
#pragma unroll
    for (int mi = 0; mi < 4; mi++) {
        int r0 = m0 + wm + mi * 16 + g;
#pragma unroll
        for (int n8 = 0; n8 < 4; n8++) {
            int c = wn + n8 * 8 + 2 * tc;
            float2 bv = *(const float2*)(b8 + c);
            float2 v01, v23;
            v01.x = fmaxf(acc[mi][n8][0] + bv.x, 0.f);
            v01.y = fmaxf(acc[mi][n8][1] + bv.y, 0.f);
            v23.x = fmaxf(acc[mi][n8][2] + bv.x, 0.f);
            v23.y = fmaxf(acc[mi][n8][3] + bv.y, 0.f);
            *(float2*)(out + (size_t)r0 * 128 + c) = v01;
            *(float2*)(out + (size_t)(r0 + 8) * 128 + c) = v23;
        }
    }
}

// ---------------- fast exp (Schraudolph); clamp low side ----------------------
__device__ __forceinline__ float fast_exp(float x) {
    x = fmaxf(x, -80.f);
    int i = (int)(fmaf(x, 12102203.0f, 1064866805.0f));
    return __int_as_float(i);
}

// ---- flash attention, bf16 HMMA, BM=128 BN=128, lagged softmax, half-split ---
#define OPITCH 132
#define ATTN_SMEM 131072   // 2 stages * (32KB K + 32KB V)

__global__ void __launch_bounds__(256, 1) attn_kernel(
    const bf16* __restrict__ gq,
    const bf16* __restrict__ gk,
    const bf16* __restrict__ gv,
    const float* __restrict__ gnv, int nv_ld,
    float* __restrict__ out) {
    extern __shared__ char smraw[];
    float* OutS = (float*)smraw;                   // reused post-loop, [128][OPITCH]

    const int tid = threadIdx.x;
    const int lane = tid & 31, w = tid >> 5;
    const int g = lane >> 2, tc = lane & 3;
    const int b = blockIdx.y;
    const int q0 = blockIdx.x * 128;

    uint32_t qa[8][4];
    {
        const bf16* Qb = gq + ((size_t)(b * NSEQ) + q0 + w * 16) * CH;
#pragma unroll
        for (int kb = 0; kb < 8; kb++) {
            qa[kb][0] = *(const uint32_t*)(Qb + (size_t)g * CH + kb * 16 + 2 * tc);
            qa[kb][1] = *(const uint32_t*)(Qb + (size_t)(g + 8) * CH + kb * 16 + 2 * tc);
            qa[kb][2] = *(const uint32_t*)(Qb + (size_t)g * CH + kb * 16 + 8 + 2 * tc);
            qa[kb][3] = *(const uint32_t*)(Qb + (size_t)(g + 8) * CH + kb * 16 + 8 + 2 * tc);
        }
    }

    float O[16][4];
#pragma unroll
    for (int i = 0; i < 16; i++)
#pragma unroll
        for (int j = 0; j < 4; j++) O[i][j] = 0.f;
    float m0s = 0.f, m1s = 0.f;           // lagged softmax shift (warp-quad uniform)
    float lrow0 = 0.f, lrow1 = 0.f;       // per-thread partial sums (reduced at end)

    const int rK_loc = ((lane >> 4) & 1) * 8 + (lane & 7);
    const int cK_bit = (lane >> 3) & 1;
    const int rV_loc = ((lane >> 3) & 1) * 8 + (lane & 7);
    const int cV_bit = lane >> 4;

    const bf16* Kgb = gk + (size_t)b * NSEQ * CH;
    const bf16* Vgb = gv + (size_t)b * NSEQ * CH;

    auto stage = [&](int jt, int s) {
        const uint4* Kg = (const uint4*)(Kgb + (size_t)jt * 128 * CH);
        const uint4* Vg = (const uint4*)(Vgb + (size_t)jt * 128 * CH);
        uint4* Kd = (uint4*)(smraw + s * 65536);
        uint4* Vd = Kd + 2048;
#pragma unroll
        for (int i = tid; i < 2048; i += 256) {
            int r = i >> 4, ch = i & 15, sch = ch ^ (r & 7);
            cpasync16(Kd + r * 16 + sch, Kg + i);
            cpasync16(Vd + r * 16 + sch, Vg + i);
        }
    };

    stage(0, 0);
    CP_COMMIT();

    for (int jt = 0; jt < NSEQ / 128; jt++) {
        if (jt + 1 < NSEQ / 128) stage(jt + 1, (jt + 1) & 1);
        CP_COMMIT();
        CP_WAIT1();
        __syncthreads();

        bf16* Ks = (bf16*)(smraw + (jt & 1) * 65536);
        bf16* Vs = Ks + 128 * 128;

        float t0 = -1e30f, t1 = -1e30f;   // tile max accumulators (per-thread)

        // process tile in two 64-wide halves: S-MMA -> exp -> pack -> PV
#pragma unroll
        for (int h = 0; h < 2; h++) {
            // ---- S_h = Q K_h^T  (16 x 64 per warp) ----
            float S[8][4];
#pragma unroll
            for (int i = 0; i < 8; i++)
#pragma unroll
                for (int j = 0; j < 4; j++) S[i][j] = 0.f;
#pragma unroll
            for (int kb = 0; kb < 8; kb++) {
#pragma unroll
                for (int p = 0; p < 4; p++) {
                    int r = (h * 4 + p) * 16 + rK_loc;
                    int ch = 2 * kb + cK_bit;
                    uint32_t b0, b1, b2, b3;
                    ldsm4(b0, b1, b2, b3, Ks + r * 128 + ((ch ^ (r & 7)) << 3));
                    uint32_t bb[2] = {b0, b1};
                    mma16816(S[2 * p], qa[kb], bb);
                    uint32_t bb2[2] = {b2, b3};
                    mma16816(S[2 * p + 1], qa[kb], bb2);
                }
            }

            // ---- per-thread half max ----
            float h0 = -1e30f, h1 = -1e30f;
#pragma unroll
            for (int nb = 0; nb < 8; nb++) {
                h0 = fmaxf(h0, fmaxf(S[nb][0], S[nb][1]));
                h1 = fmaxf(h1, fmaxf(S[nb][2], S[nb][3]));
            }
            if (jt == 0 && h == 0) {
                // initialize shift eagerly from half 0 of tile 0
                float u0 = fmaxf(h0, __shfl_xor_sync(0xffffffffu, h0, 1));
                u0 = fmaxf(u0, __shfl_xor_sync(0xffffffffu, u0, 2));
                float u1 = fmaxf(h1, __shfl_xor_sync(0xffffffffu, h1, 1));
                u1 = fmaxf(u1, __shfl_xor_sync(0xffffffffu, u1, 2));
                m0s = u0 + 4.f;
                m1s = u1 + 4.f;
            }
            t0 = fmaxf(t0, h0);
            t1 = fmaxf(t1, h1);

            // ---- exps with lagged (uniform) shift; per-thread sum; pack ----
            uint32_t pa[4][4];
#pragma unroll
            for (int nb = 0; nb < 8; nb++) {
                S[nb][0] = fast_exp(S[nb][0] - m0s);
                S[nb][1] = fast_exp(S[nb][1] - m0s);
                S[nb][2] = fast_exp(S[nb][2] - m1s);
                S[nb][3] = fast_exp(S[nb][3] - m1s);
                lrow0 += S[nb][0] + S[nb][1];
                lrow1 += S[nb][2] + S[nb][3];
            }
#pragma unroll
            for (int jb = 0; jb < 4; jb++) {
                pa[jb][0] = packbf2(S[2 * jb][0], S[2 * jb][1]);
                pa[jb][1] = packbf2(S[2 * jb][2], S[2 * jb][3]);
                pa[jb][2] = packbf2(S[2 * jb + 1][0], S[2 * jb + 1][1]);
                pa[jb][3] = packbf2(S[2 * jb + 1][2], S[2 * jb + 1][3]);
            }

            // ---- O += P_h · V_h ----
#pragma unroll
            for (int jb = 0; jb < 4; jb++) {
                int r = (h * 4 + jb) * 16 + rV_loc;
#pragma unroll
                for (int cp = 0; cp < 8; cp++) {
                    int ch = 2 * cp + cV_bit;
                    uint32_t b0, b1, b2, b3;
                    ldsm4t(b0, b1, b2, b3, Vs + r * 128 + ((ch ^ (r & 7)) << 3));
                    uint32_t bb[2] = {b0, b1};
                    mma16816(O[2 * cp], pa[jb], bb);
                    uint32_t bb2[2] = {b2, b3};
                    mma16816(O[2 * cp + 1], pa[jb], bb2);
                }
            }
        }

        // ---- merge tile max into shift for NEXT iteration (off critical path) ----
        if (jt + 1 < NSEQ / 128) {
            float u0 = fmaxf(t0, __shfl_xor_sync(0xffffffffu, t0, 1));
            u0 = fmaxf(u0, __shfl_xor_sync(0xffffffffu, u0, 2));
            float u1 = fmaxf(t1, __shfl_xor_sync(0xffffffffu, t1, 1));
            u1 = fmaxf(u1, __shfl_xor_sync(0xffffffffu, u1, 2));
            bool inc = (u0 > m0s) | (u1 > m1s);
            if (__any_sync(0xffffffffu, inc)) {
                float nm0 = u0 > m0s ? u0 + 4.f : m0s;
                float nm1 = u1 > m1s ? u1 + 4.f : m1s;
                // uniform per-row-pair scale applied to both O and lrow -> exact
                float scl0 = fast_exp(m0s - nm0), scl1 = fast_exp(m1s - nm1);
                lrow0 *= scl0; lrow1 *= scl1;
#pragma unroll
                for (int nb = 0; nb < 16; nb++) {
                    O[nb][0] *= scl0; O[nb][1] *= scl0;
                    O[nb][2] *= scl1; O[nb][3] *= scl1;
                }
                m0s = nm0; m1s = nm1;
            }
        }
        __syncthreads();
    }

    // ---- final lrow reduction (once) ----
    lrow0 += __shfl_xor_sync(0xffffffffu, lrow0, 1);
    lrow0 += __shfl_xor_sync(0xffffffffu, lrow0, 2);
    lrow1 += __shfl_xor_sync(0xffffffffu, lrow1, 1);
    lrow1 += __shfl_xor_sync(0xffffffffu, lrow1, 2);

    // ---- epilogue ----
    {
        float inv0 = 1.f / lrow0, inv1 = 1.f / lrow1;
        int row0 = w * 16 + g, row1 = row0 + 8;
        const float* nvp0 = gnv + ((size_t)(b * NSEQ) + q0 + row0) * nv_ld;
        const float* nvp1 = gnv + ((size_t)(b * NSEQ) + q0 + row1) * nv_ld;
#pragma unroll
        for (int nb = 0; nb < 16; nb++) {
            int c = nb * 8 + 2 * tc;
            float2 nv0 = *(const float2*)(nvp0 + c);
            float2 nv1 = *(const float2*)(nvp1 + c);
            OutS[c * OPITCH + row0] = fmaf(THITA, O[nb][0] * inv0, nv0.x);
            OutS[(c + 1) * OPITCH + row0] = fmaf(THITA, O[nb][1] * inv0, nv0.y);
            OutS[c * OPITCH + row1] = fmaf(THITA, O[nb][2] * inv1, nv1.x);
            OutS[(c + 1) * OPITCH + row1] = fmaf(THITA, O[nb][3] * inv1, nv1.y);
        }
    }
    __syncthreads();
    {
        float* ob = out + (size_t)b * CH * NSEQ + q0;
        for (int i = tid; i < 128 * 128 / 4; i += 256) {
            int idx = i * 4;
            int c = idx >> 7, nl = idx & 127;
            float4 v = *(const float4*)(OutS + c * OPITCH + nl);
            *(float4*)(ob + (size_t)c * NSEQ + nl) = v;
        }
    }
}

// ---------------- host launch --------------------------------------------------
extern "C" void kernel_launch(void* const* d_in, const int* in_sizes, int n_in,
                              void* d_out, int out_size) {
    const float* event = (const float*)d_in[0];
    const float* W[12];
    const float* Bv[12];
    for (int i = 0; i < 12; i++) {
        W[i] = (const float*)d_in[1 + 2 * i];
        Bv[i] = (const float*)d_in[2 + 2 * i];
    }

    float *nowval, *bc1, *bc2;
    bf16 *qb, *kb, *vb;
    bf16 *wb1, *wb2, *wbt, *wbnk, *wbq, *wbk, *wbv, *w8hi, *w8lo;
    cudaGetSymbolAddress((void**)&nowval, g_nowval);
    cudaGetSymbolAddress((void**)&qb, g_qb);
    cudaGetSymbolAddress((void**)&kb, g_kb);
    cudaGetSymbolAddress((void**)&vb, g_vb);
    cudaGetSymbolAddress((void**)&wb1, g_wb1);
    cudaGetSymbolAddress((void**)&wb2, g_wb2);
    cudaGetSymbolAddress((void**)&wbt, g_wbt);
    cudaGetSymbolAddress((void**)&wbnk, g_wbnk);
    cudaGetSymbolAddress((void**)&wbq, g_wbq);
    cudaGetSymbolAddress((void**)&wbk, g_wbk);
    cudaGetSymbolAddress((void**)&wbv, g_wbv);
    cudaGetSymbolAddress((void**)&w8hi, g_w8hi);
    cudaGetSymbolAddress((void**)&w8lo, g_w8lo);
    cudaGetSymbolAddress((void**)&bc1, g_bc1);
    cudaGetSymbolAddress((void**)&bc2, g_bc2);

    cudaFuncSetAttribute(attn_kernel, cudaFuncAttributeMaxDynamicSharedMemorySize, ATTN_SMEM);
    cudaFuncSetAttribute(gemm_nowval, cudaFuncAttributeMaxDynamicSharedMemorySize, NV_SMEM);
    cudaFuncSetAttribute(fused_conv_kernel, cudaFuncAttributeMaxDynamicSharedMemorySize, FUSED_SMEM);

    prep_w_kernel<<<640, 256>>>(W[1], W[3], W[2], W[4], W[5], W[7], W[9], W[10], W[11], W[8],
                                Bv[1], Bv[3], Bv[2], Bv[4]);

    fused_conv_kernel<<<PIX / 128, 256, FUSED_SMEM>>>(
        event, W[0], Bv[0], W[6], Bv[6],
        wb1, bc1, wb2, bc2, wbt, Bv[5], wbnk, Bv[7],
        wbq, Bv[9], wbk, Bv[10], wbv, Bv[11],
        qb, kb, vb);

    gemm_nowval<<<PIX / 128, 256, NV_SMEM>>>(event, W[6], Bv[6], w8hi, w8lo, Bv[8], nowval);

    attn_kernel<<<dim3(NSEQ / 128, BSZ), 256, ATTN_SMEM>>>(qb, kb, vb, nowval, 128,
                                                           (float*)d_out);
}

// round 14
// speedup vs baseline: 1.0386x; 1.0386x over previous
#include <cuda_runtime.h>
#include <cuda_bf16.h>
#include <cstdint>

// Problem constants
#define PIX 16384        // B*H*W
#define NSEQ 4096        // H*W
#define BSZ 4
#define CH 128
#define THITA 1e-4f

typedef __nv_bfloat16 bf16;

// ---------------- scratch (device globals; no allocation allowed) -------------
__device__ float g_nowval[PIX * 128];
__device__ bf16 g_qb[PIX * 128];
__device__ bf16 g_kb[PIX * 128];
__device__ bf16 g_vb[PIX * 128];
// bf16 weights
__device__ bf16 g_wb1[256 * 128];   // [w_pro_key ; w_lat_key]
__device__ bf16 g_wb2[256 * 128];   // [w_pro_val ; w_lat_val]
__device__ bf16 g_wbt[128 * 256];   // w_tmp1
__device__ bf16 g_wbnk[128 * 128];  // w_now_key
__device__ bf16 g_wbq[128 * 128];
__device__ bf16 g_wbk[128 * 128];
__device__ bf16 g_wbv[128 * 128];
__device__ bf16 g_w8hi[128 * 128];  // w_now_val split hi
__device__ bf16 g_w8lo[128 * 128];  // w_now_val split lo
__device__ float g_bc1[256];
__device__ float g_bc2[256];

// ---------------- weight prep ---------------------------------------------------
__global__ void __launch_bounds__(256) prep_w_kernel(
    const float* __restrict__ wpk, const float* __restrict__ wlk,
    const float* __restrict__ wpv, const float* __restrict__ wlv,
    const float* __restrict__ wt,  const float* __restrict__ wnk,
    const float* __restrict__ wq,  const float* __restrict__ wk,
    const float* __restrict__ wv,  const float* __restrict__ wnv,
    const float* __restrict__ bpk, const float* __restrict__ blk,
    const float* __restrict__ bpv, const float* __restrict__ blv) {
    int i = blockIdx.x * blockDim.x + threadIdx.x;   // 0..163839
    if (i < 32768) {
        g_wb1[i] = __float2bfloat16(i < 16384 ? wpk[i] : wlk[i - 16384]);
        g_wb2[i] = __float2bfloat16(i < 16384 ? wpv[i] : wlv[i - 16384]);
        g_wbt[i] = __float2bfloat16(wt[i]);
    } else if (i < 49152) {
        int j = i - 32768;
        if (j < 16384) {
            g_wbnk[j] = __float2bfloat16(wnk[j]);
            float v = wnv[j];
            bf16 h = __float2bfloat16(v);
            g_w8hi[j] = h;
            g_w8lo[j] = __float2bfloat16(v - __bfloat162float(h));
        }
    } else if (i < 65536) {
        int j = i - 49152;
        g_wbq[j] = __float2bfloat16(wq[j]);
        g_wbk[j] = __float2bfloat16(wk[j]);
        g_wbv[j] = __float2bfloat16(wv[j]);
    }
    if (i < 256) {
        g_bc1[i] = i < 128 ? bpk[i] : blk[i - 128];
        g_bc2[i] = i < 128 ? bpv[i] : blv[i - 128];
    }
}

// ---------------- mma / ldmatrix helpers --------------------------------------
__device__ __forceinline__ void mma16816(float* c, const uint32_t* a, const uint32_t* b) {
    asm volatile(
        "mma.sync.aligned.m16n8k16.row.col.f32.bf16.bf16.f32 "
        "{%0,%1,%2,%3}, {%4,%5,%6,%7}, {%8,%9}, {%0,%1,%2,%3};"
        : "+f"(c[0]), "+f"(c[1]), "+f"(c[2]), "+f"(c[3])
        : "r"(a[0]), "r"(a[1]), "r"(a[2]), "r"(a[3]), "r"(b[0]), "r"(b[1]));
}

__device__ __forceinline__ void ldsm4(uint32_t& r0, uint32_t& r1, uint32_t& r2, uint32_t& r3,
                                      const void* p) {
    uint32_t addr = (uint32_t)__cvta_generic_to_shared(p);
    asm volatile("ldmatrix.sync.aligned.m8n8.x4.shared.b16 {%0,%1,%2,%3}, [%4];"
                 : "=r"(r0), "=r"(r1), "=r"(r2), "=r"(r3) : "r"(addr));
}

__device__ __forceinline__ void ldsm4t(uint32_t& r0, uint32_t& r1, uint32_t& r2, uint32_t& r3,
                                       const void* p) {
    uint32_t addr = (uint32_t)__cvta_generic_to_shared(p);
    asm volatile("ldmatrix.sync.aligned.m8n8.x4.trans.shared.b16 {%0,%1,%2,%3}, [%4];"
                 : "=r"(r0), "=r"(r1), "=r"(r2), "=r"(r3) : "r"(addr));
}

__device__ __forceinline__ uint32_t packbf2(float lo, float hi) {
    uint32_t d;
    asm("cvt.rn.bf16x2.f32 %0, %1, %2;" : "=r"(d) : "f"(hi), "f"(lo));
    return d;
}

__device__ __forceinline__ void cpasync16(void* dst, const void* src) {
    uint32_t d = (uint32_t)__cvta_generic_to_shared(dst);
    asm volatile("cp.async.cg.shared.global [%0], [%1], 16;" :: "r"(d), "l"(src));
}
#define CP_COMMIT() asm volatile("cp.async.commit_group;")
#define CP_WAIT0()  asm volatile("cp.async.wait_group 0;")
#define CP_WAIT1()  asm volatile("cp.async.wait_group 1;")

// ============ fused conv chain (validated) =====================================
template <int K>
__device__ __forceinline__ void stage_gemm(
    const bf16* __restrict__ inb,
    const bf16* __restrict__ wg,
    const float* __restrict__ bias,
    bf16* __restrict__ wbuf,
    bf16* __restrict__ outb,
    bf16* __restrict__ outg,
    int m0, int tid) {
    const int lane = tid & 31, wid = tid >> 5;
    const int wm = (wid & 1) * 64, wn = (wid >> 1) * 32;
    const int g = lane >> 2, tc = lane & 3;
    const int rA_loc = ((lane >> 3) & 1) * 8 + (lane & 7);
    const int cA_bit = (lane >> 4) & 1;
    const int rB_loc = ((lane >> 4) & 1) * 8 + (lane & 7);
    const int cB_bit = (lane >> 3) & 1;
    constexpr int CPR = K >> 3;

#pragma unroll
    for (int i = tid; i < 128 * CPR; i += 256) {
        int n = i / CPR, ck = i % CPR;
        int kb = ck >> 3, c8 = ck & 7;
        cpasync16((uint4*)wbuf + kb * 1024 + n * 8 + (c8 ^ (n & 7)),
                  (const uint4*)wg + i);
    }
    CP_COMMIT();
    CP_WAIT0();
    __syncthreads();

    float acc[4][4][4];
#pragma unroll
    for (int i = 0; i < 4; i++)
#pragma unroll
        for (int j = 0; j < 4; j++)
#pragma unroll
            for (int l = 0; l < 4; l++) acc[i][j][l] = 0.f;

#pragma unroll
    for (int kb = 0; kb < K / 64; kb++) {
        const bf16* As = inb + kb * 8192;
        const bf16* Bs = wbuf + kb * 8192;
#pragma unroll
        for (int ks = 0; ks < 4; ks++) {
            uint32_t a[4][4], bf[2][4];
#pragma unroll
            for (int mi = 0; mi < 4; mi++) {
                int r = wm + mi * 16 + rA_loc;
                int ch = 2 * ks + cA_bit;
                ldsm4(a[mi][0], a[mi][1], a[mi][2], a[mi][3],
                      As + r * 64 + ((ch ^ (r & 7)) << 3));
            }
#pragma unroll
            for (int ni = 0; ni < 2; ni++) {
                int r = wn + ni * 16 + rB_loc;
                int ch = 2 * ks + cB_bit;
                ldsm4(bf[ni][0], bf[ni][1], bf[ni][2], bf[ni][3],
                      Bs + r * 64 + ((ch ^ (r & 7)) << 3));
            }
#pragma unroll
            for (int mi = 0; mi < 4; mi++)
#pragma unroll
                for (int ni = 0; ni < 2; ni++) {
                    uint32_t b0[2] = {bf[ni][0], bf[ni][1]};
                    mma16816(acc[mi][2 * ni], a[mi], b0);
                    uint32_t b1[2] = {bf[ni][2], bf[ni][3]};
                    mma16816(acc[mi][2 * ni + 1], a[mi], b1);
                }
        }
    }

#pragma unroll
    for (int mi = 0; mi < 4; mi++) {
        int r0 = wm + mi * 16 + g;
#pragma unroll
        for (int n8 = 0; n8 < 4; n8++) {
            int c = wn + n8 * 8 + 2 * tc;
            float2 bv = *(const float2*)(bias + c);
            uint32_t p0 = packbf2(fmaxf(acc[mi][n8][0] + bv.x, 0.f),
                                  fmaxf(acc[mi][n8][1] + bv.y, 0.f));
            uint32_t p1 = packbf2(fmaxf(acc[mi][n8][2] + bv.x, 0.f),
                                  fmaxf(acc[mi][n8][3] + bv.y, 0.f));
            if (outb) {
                int kb_o = c >> 6, cl = c & 63, chk = cl >> 3, off = cl & 7;
                bf16* base = outb + kb_o * 8192;
                *(uint32_t*)(base + r0 * 64 + ((chk ^ (r0 & 7)) << 3) + off) = p0;
                int r1 = r0 + 8;
                *(uint32_t*)(base + r1 * 64 + ((chk ^ (r1 & 7)) << 3) + off) = p1;
            } else {
                *(uint32_t*)(outg + (size_t)(m0 + r0) * 128 + c) = p0;
                *(uint32_t*)(outg + (size_t)(m0 + r0 + 8) * 128 + c) = p1;
            }
        }
    }
    __syncthreads();
}

#define FUSED_SMEM (65536 + 65536 + 32768 + 65536)   // A,B,C,W = 229376 B

__global__ void __launch_bounds__(256, 1) fused_conv_kernel(
    const float* __restrict__ event,
    const float* __restrict__ w0, const float* __restrict__ b0,
    const float* __restrict__ w6, const float* __restrict__ b6,
    const bf16* __restrict__ wb1, const float* __restrict__ bc1,
    const bf16* __restrict__ wb2, const float* __restrict__ bc2,
    const bf16* __restrict__ wbt, const float* __restrict__ bt,
    const bf16* __restrict__ wbnk, const float* __restrict__ bnk,
    const bf16* __restrict__ wbq, const float* __restrict__ bq,
    const bf16* __restrict__ wbk, const float* __restrict__ bk,
    const bf16* __restrict__ wbv, const float* __restrict__ bv,
    const bf16* __restrict__ w8hi, const bf16* __restrict__ w8lo,
    const float* __restrict__ b8,
    bf16* __restrict__ qb, bf16* __restrict__ kb_, bf16* __restrict__ vb,
    float* __restrict__ nowval) {
    extern __shared__ char sm[];
    bf16* A = (bf16*)sm;
    bf16* B = (bf16*)(sm + 65536);
    bf16* C = (bf16*)(sm + 131072);
    bf16* W = (bf16*)(sm + 163840);
    const int tid = threadIdx.x, lane = tid & 31, wid = tid >> 5;
    const int m0 = blockIdx.x * 128;
    const float* ev = event + (size_t)(m0 >> 12) * 6 * NSEQ + (m0 & 4095);

    // ---- neigh (K=4 conv) -> A, 256 ch ----
    for (int i = tid; i < 4096; i += 256) {
        int r = i >> 5, ck = i & 31;
        float x0 = ev[r], x1 = ev[NSEQ + r], x2 = ev[4 * NSEQ + r], x3 = ev[5 * NSEQ + r];
        uint32_t pk[4];
#pragma unroll
        for (int j = 0; j < 4; j++) {
            int c0 = ck * 8 + 2 * j, c1 = c0 + 1;
            float v0 = fmaf(w0[c0 * 4 + 3], x3, fmaf(w0[c0 * 4 + 2], x2,
                       fmaf(w0[c0 * 4 + 1], x1, fmaf(w0[c0 * 4], x0, b0[c0]))));
            float v1 = fmaf(w0[c1 * 4 + 3], x3, fmaf(w0[c1 * 4 + 2], x2,
                       fmaf(w0[c1 * 4 + 1], x1, fmaf(w0[c1 * 4], x0, b0[c1]))));
            pk[j] = packbf2(fmaxf(v0, 0.f), fmaxf(v1, 0.f));
        }
        ((uint4*)A)[(ck >> 3) * 1024 + r * 8 + ((ck & 7) ^ (r & 7))] =
            make_uint4(pk[0], pk[1], pk[2], pk[3]);
    }
    __syncthreads();

    stage_gemm<128>(A, wb1, bc1, W, B, nullptr, m0, tid);
    stage_gemm<128>(A, wb1 + 128 * 128, bc1 + 128, W, B + 2 * 8192, nullptr, m0, tid);
    stage_gemm<256>(B, wbt, bt, W, C, nullptr, m0, tid);
    stage_gemm<128>(C, wbq, bq, W, nullptr, qb, m0, tid);

    stage_gemm<128>(A + 2 * 8192, wb2, bc2, W, B, nullptr, m0, tid);
    stage_gemm<128>(A + 2 * 8192, wb2 + 128 * 128, bc2 + 128, W, B + 2 * 8192, nullptr, m0, tid);
    stage_gemm<256>(B, wbt, bt, W, C, nullptr, m0, tid);
    stage_gemm<128>(C, wbv, bv, W, nullptr, vb, m0, tid);

    // ---- nowf (K=2 conv) -> A kb0-1 (bf16) ; nowkey -> C ; k -> global ----
    for (int i = tid; i < 2048; i += 256) {
        int r = i >> 4, ck = i & 15;
        float x = ev[2 * NSEQ + r], y = ev[3 * NSEQ + r];
        uint32_t pk[4];
#pragma unroll
        for (int j = 0; j < 4; j++) {
            int c0 = ck * 8 + 2 * j, c1 = c0 + 1;
            float v0 = fmaxf(fmaf(w6[c0 * 2 + 1], y, fmaf(w6[c0 * 2], x, b6[c0])), 0.f);
            float v1 = fmaxf(fmaf(w6[c1 * 2 + 1], y, fmaf(w6[c1 * 2], x, b6[c1])), 0.f);
            pk[j] = packbf2(v0, v1);
        }
        ((uint4*)A)[(ck >> 3) * 1024 + r * 8 + ((ck & 7) ^ (r & 7))] =
            make_uint4(pk[0], pk[1], pk[2], pk[3]);
    }
    __syncthreads();
    stage_gemm<128>(A, wbnk, bnk, W, C, nullptr, m0, tid);
    stage_gemm<128>(C, wbk, bk, W, nullptr, kb_, m0, tid);

    // ================= nowval phase (was gemm_nowval kernel) ==================
    // A region hosts Ah/Al/Bh/Bl (4 x 16KB); aux floats in B region.
    {
        bf16* Ah = A;
        bf16* Al = A + 8192;
        bf16* Bh = A + 16384;
        bf16* Bl = A + 24576;
        float* x2s = (float*)B;            // [128][2]
        float* w6s = x2s + 256;            // [128][2]
        float* b6s = w6s + 256;            // [128]

        const int wm = (wid & 1) * 64, wn = (wid >> 1) * 32;
        const int g = lane >> 2, tc = lane & 3;
        const int rA_loc = ((lane >> 3) & 1) * 8 + (lane & 7);
        const int cA_bit = (lane >> 4) & 1;
        const int rB_loc = ((lane >> 4) & 1) * 8 + (lane & 7);
        const int cB_bit = (lane >> 3) & 1;

        if (tid < 128) {
            x2s[2 * tid] = ev[2 * NSEQ + tid];
            x2s[2 * tid + 1] = ev[3 * NSEQ + tid];
            b6s[tid] = b6[tid];
        } else {
            int j = tid - 128;
            ((float2*)w6s)[j] = ((const float2*)w6)[j];
        }
        __syncthreads();

        float acc[4][4][4];
#pragma unroll
        for (int i = 0; i < 4; i++)
#pragma unroll
            for (int j = 0; j < 4; j++)
#pragma unroll
                for (int l = 0; l < 4; l++) acc[i][j][l] = 0.f;

        for (int k0 = 0; k0 < 128; k0 += 64) {
#pragma unroll
            for (int i = 0; i < 4; i++) {
                int li = tid + i * 256;
                int r = li >> 3, cch = li & 7;
                float x0 = x2s[2 * r], x1 = x2s[2 * r + 1];
                uint4 hq, lq;
                bf16* hp = (bf16*)&hq;
                bf16* lp = (bf16*)&lq;
#pragma unroll
                for (int j = 0; j < 8; j++) {
                    int k = k0 + cch * 8 + j;
                    float v = fmaxf(fmaf(w6s[2 * k + 1], x1, fmaf(w6s[2 * k], x0, b6s[k])), 0.f);
                    bf16 h = __float2bfloat16(v);
                    hp[j] = h;
                    lp[j] = __float2bfloat16(v - __bfloat162float(h));
                }
                int sidx = r * 8 + (cch ^ (r & 7));
                ((uint4*)Ah)[sidx] = hq;
                ((uint4*)Al)[sidx] = lq;
                ((uint4*)Bh)[sidx] = *(const uint4*)(w8hi + (size_t)r * 128 + k0 + cch * 8);
                ((uint4*)Bl)[sidx] = *(const uint4*)(w8lo + (size_t)r * 128 + k0 + cch * 8);
            }
            __syncthreads();
#pragma unroll
            for (int ks = 0; ks < 4; ks++) {
                uint32_t ah[4][4], al[4][4], bh[2][4], bl[2][4];
#pragma unroll
                for (int mi = 0; mi < 4; mi++) {
                    int r = wm + mi * 16 + rA_loc;
                    int ch = 2 * ks + cA_bit;
                    int off = r * 64 + ((ch ^ (r & 7)) << 3);
                    ldsm4(ah[mi][0], ah[mi][1], ah[mi][2], ah[mi][3], Ah + off);
                    ldsm4(al[mi][0], al[mi][1], al[mi][2], al[mi][3], Al + off);
                }
#pragma unroll
                for (int ni = 0; ni < 2; ni++) {
                    int r = wn + ni * 16 + rB_loc;
                    int ch = 2 * ks + cB_bit;
                    int off = r * 64 + ((ch ^ (r & 7)) << 3);
                    ldsm4(bh[ni][0], bh[ni][1], bh[ni][2], bh[ni][3], Bh + off);
                    ldsm4(bl[ni][0], bl[ni][1], bl[ni][2], bl[ni][3], Bl + off);
                }
#pragma unroll
                for (int mi = 0; mi < 4; mi++)
#pragma unroll
                    for (int ni = 0; ni < 2; ni++) {
                        uint32_t h0[2] = {bh[ni][0], bh[ni][1]};
                        uint32_t h1[2] = {bh[ni][2], bh[ni][3]};
                        uint32_t l0[2] = {bl[ni][0], bl[ni][1]};
                        uint32_t l1[2] = {bl[ni][2], bl[ni][3]};
                        mma16816(acc[mi][2 * ni], ah[mi], h0);
                        mma16816(acc[mi][2 * ni + 1], ah[mi], h1);
                        mma16816(acc[mi][2 * ni], ah[mi], l0);
                        mma16816(acc[mi][2 * ni + 1], ah[mi], l1);
                        mma16816(acc[mi][2 * ni], al[mi], h0);
                        mma16816(acc[mi][2 * ni + 1], al[mi], h1);
                    }
            }
            __syncthreads();
        }
#pragma unroll
        for (int mi = 0; mi < 4; mi++) {
            int r0 = m0 + wm + mi * 16 + g;
#pragma unroll
            for (int n8 = 0; n8 < 4; n8++) {
                int c = wn + n8 * 8 + 2 * tc;
                float2 bv = *(const float2*)(b8 + c);
                float2 v01, v23;
                v01.x = fmaxf(acc[mi][n8][0] + bv.x, 0.f);
                v01.y = fmaxf(acc[mi][n8][1] + bv.y, 0.f);
                v23.x = fmaxf(acc[mi][n8][2] + bv.x, 0.f);
                v23.y = fmaxf(acc[mi][n8][3] + bv.y, 0.f);
                *(float2*)(nowval + (size_t)r0 * 128 + c) = v01;
                *(float2*)(nowval + (size_t)(r0 + 8) * 128 + c) = v23;
            }
        }
    }
}

// ---------------- fast exp (Schraudolph); clamp low side ----------------------
__device__ __forceinline__ float fast_exp(float x) {
    x = fmaxf(x, -80.f);
    int i = (int)(fmaf(x, 12102203.0f, 1064866805.0f));
    return __int_as_float(i);
}

// ---- flash attention, bf16 HMMA, BM=128 BN=128, lagged softmax (round-11) ----
#define OPITCH 132
#define ATTN_SMEM 131072   // 2 stages * (32KB K + 32KB V)

__global__ void __launch_bounds__(256, 1) attn_kernel(
    const bf16* __restrict__ gq,
    const bf16* __restrict__ gk,
    const bf16* __restrict__ gv,
    const float* __restrict__ gnv, int nv_ld,
    float* __restrict__ out) {
    extern __shared__ char smraw[];
    float* OutS = (float*)smraw;                   // reused post-loop, [128][OPITCH]

    const int tid = threadIdx.x;
    const int lane = tid & 31, w = tid >> 5;
    const int g = lane >> 2, tc = lane & 3;
    const int b = blockIdx.y;
    const int q0 = blockIdx.x * 128;

    uint32_t qa[8][4];
    {
        const bf16* Qb = gq + ((size_t)(b * NSEQ) + q0 + w * 16) * CH;
#pragma unroll
        for (int kb = 0; kb < 8; kb++) {
            qa[kb][0] = *(const uint32_t*)(Qb + (size_t)g * CH + kb * 16 + 2 * tc);
            qa[kb][1] = *(const uint32_t*)(Qb + (size_t)(g + 8) * CH + kb * 16 + 2 * tc);
            qa[kb][2] = *(const uint32_t*)(Qb + (size_t)g * CH + kb * 16 + 8 + 2 * tc);
            qa[kb][3] = *(const uint32_t*)(Qb + (size_t)(g + 8) * CH + kb * 16 + 8 + 2 * tc);
        }
    }

    float O[16][4];
#pragma unroll
    for (int i = 0; i < 16; i++)
#pragma unroll
        for (int j = 0; j < 4; j++) O[i][j] = 0.f;
    float m0s = 0.f, m1s = 0.f;           // lagged softmax shift (warp-quad uniform)
    float lrow0 = 0.f, lrow1 = 0.f;       // per-thread partial sums (reduced at end)

    const int rK_loc = ((lane >> 4) & 1) * 8 + (lane & 7);
    const int cK_bit = (lane >> 3) & 1;
    const int rV_loc = ((lane >> 3) & 1) * 8 + (lane & 7);
    const int cV_bit = lane >> 4;

    const bf16* Kgb = gk + (size_t)b * NSEQ * CH;
    const bf16* Vgb = gv + (size_t)b * NSEQ * CH;

    auto stage = [&](int jt, int s) {
        const uint4* Kg = (const uint4*)(Kgb + (size_t)jt * 128 * CH);
        const uint4* Vg = (const uint4*)(Vgb + (size_t)jt * 128 * CH);
        uint4* Kd = (uint4*)(smraw + s * 65536);
        uint4* Vd = Kd + 2048;
#pragma unroll
        for (int i = tid; i < 2048; i += 256) {
            int r = i >> 4, ch = i & 15, sch = ch ^ (r & 7);
            cpasync16(Kd + r * 16 + sch, Kg + i);
            cpasync16(Vd + r * 16 + sch, Vg + i);
        }
    };

    stage(0, 0);
    CP_COMMIT();

    for (int jt = 0; jt < NSEQ / 128; jt++) {
        if (jt + 1 < NSEQ / 128) stage(jt + 1, (jt + 1) & 1);
        CP_COMMIT();
        CP_WAIT1();
        __syncthreads();

        bf16* Ks = (bf16*)(smraw + (jt & 1) * 65536);
        bf16* Vs = Ks + 128 * 128;

        // ---- S = Q K^T  (16 x 128 per warp) ----
        float S[16][4];
#pragma unroll
        for (int i = 0; i < 16; i++)
#pragma unroll
            for (int j = 0; j < 4; j++) S[i][j] = 0.f;
#pragma unroll
        for (int kb = 0; kb < 8; kb++) {
#pragma unroll
            for (int p = 0; p < 8; p++) {
                int r = p * 16 + rK_loc;
                int ch = 2 * kb + cK_bit;
                uint32_t b0, b1, b2, b3;
                ldsm4(b0, b1, b2, b3, Ks + r * 128 + ((ch ^ (r & 7)) << 3));
                uint32_t bb[2] = {b0, b1};
                mma16816(S[2 * p], qa[kb], bb);
                uint32_t bb2[2] = {b2, b3};
                mma16816(S[2 * p + 1], qa[kb], bb2);
            }
        }

        // ---- per-thread tile max (no shuffles on critical path) ----
        float t0 = -1e30f, t1 = -1e30f;
#pragma unroll
        for (int nb = 0; nb < 16; nb++) {
            t0 = fmaxf(t0, fmaxf(S[nb][0], S[nb][1]));
            t1 = fmaxf(t1, fmaxf(S[nb][2], S[nb][3]));
        }
        if (jt == 0) {
            float u0 = fmaxf(t0, __shfl_xor_sync(0xffffffffu, t0, 1));
            u0 = fmaxf(u0, __shfl_xor_sync(0xffffffffu, u0, 2));
            float u1 = fmaxf(t1, __shfl_xor_sync(0xffffffffu, t1, 1));
            u1 = fmaxf(u1, __shfl_xor_sync(0xffffffffu, u1, 2));
            m0s = u0 + 4.f;
            m1s = u1 + 4.f;
        }

        // ---- exps with lagged (uniform) shift; per-thread sum accumulation ----
#pragma unroll
        for (int nb = 0; nb < 16; nb++) {
            S[nb][0] = fast_exp(S[nb][0] - m0s);
            S[nb][1] = fast_exp(S[nb][1] - m0s);
            S[nb][2] = fast_exp(S[nb][2] - m1s);
            S[nb][3] = fast_exp(S[nb][3] - m1s);
            lrow0 += S[nb][0] + S[nb][1];
            lrow1 += S[nb][2] + S[nb][3];
        }

        // ---- P fragments ----
        uint32_t pa[8][4];
#pragma unroll
        for (int jb = 0; jb < 8; jb++) {
            pa[jb][0] = packbf2(S[2 * jb][0], S[2 * jb][1]);
            pa[jb][1] = packbf2(S[2 * jb][2], S[2 * jb][3]);
            pa[jb][2] = packbf2(S[2 * jb + 1][0], S[2 * jb + 1][1]);
            pa[jb][3] = packbf2(S[2 * jb + 1][2], S[2 * jb + 1][3]);
        }

        // ---- O += P V ----
#pragma unroll
        for (int jb = 0; jb < 8; jb++) {
            int r = jb * 16 + rV_loc;
#pragma unroll
            for (int cp = 0; cp < 8; cp++) {
                int ch = 2 * cp + cV_bit;
                uint32_t b0, b1, b2, b3;
                ldsm4t(b0, b1, b2, b3, Vs + r * 128 + ((ch ^ (r & 7)) << 3));
                uint32_t bb[2] = {b0, b1};
                mma16816(O[2 * cp], pa[jb], bb);
                uint32_t bb2[2] = {b2, b3};
                mma16816(O[2 * cp + 1], pa[jb], bb2);
            }
        }

        // ---- merge tile max into shift for NEXT iteration (off critical path) ----
        if (jt > 0 && jt + 1 < NSEQ / 128) {
            float u0 = fmaxf(t0, __shfl_xor_sync(0xffffffffu, t0, 1));
            u0 = fmaxf(u0, __shfl_xor_sync(0xffffffffu, u0, 2));
            float u1 = fmaxf(t1, __shfl_xor_sync(0xffffffffu, t1, 1));
            u1 = fmaxf(u1, __shfl_xor_sync(0xffffffffu, u1, 2));
            bool inc = (u0 > m0s) | (u1 > m1s);
            if (__any_sync(0xffffffffu, inc)) {
                float nm0 = u0 > m0s ? u0 + 4.f : m0s;
                float nm1 = u1 > m1s ? u1 + 4.f : m1s;
                float scl0 = fast_exp(m0s - nm0), scl1 = fast_exp(m1s - nm1);
                lrow0 *= scl0; lrow1 *= scl1;
#pragma unroll
                for (int nb = 0; nb < 16; nb++) {
                    O[nb][0] *= scl0; O[nb][1] *= scl0;
                    O[nb][2] *= scl1; O[nb][3] *= scl1;
                }
                m0s = nm0; m1s = nm1;
            }
        }
        __syncthreads();
    }

    // ---- final lrow reduction (once) ----
    lrow0 += __shfl_xor_sync(0xffffffffu, lrow0, 1);
    lrow0 += __shfl_xor_sync(0xffffffffu, lrow0, 2);
    lrow1 += __shfl_xor_sync(0xffffffffu, lrow1, 1);
    lrow1 += __shfl_xor_sync(0xffffffffu, lrow1, 2);

    // ---- epilogue ----
    {
        float inv0 = 1.f / lrow0, inv1 = 1.f / lrow1;
        int row0 = w * 16 + g, row1 = row0 + 8;
        const float* nvp0 = gnv + ((size_t)(b * NSEQ) + q0 + row0) * nv_ld;
        const float* nvp1 = gnv + ((size_t)(b * NSEQ) + q0 + row1) * nv_ld;
#pragma unroll
        for (int nb = 0; nb < 16; nb++) {
            int c = nb * 8 + 2 * tc;
            float2 nv0 = *(const float2*)(nvp0 + c);
            float2 nv1 = *(const float2*)(nvp1 + c);
            OutS[c * OPITCH + row0] = fmaf(THITA, O[nb][0] * inv0, nv0.x);
            OutS[(c + 1) * OPITCH + row0] = fmaf(THITA, O[nb][1] * inv0, nv0.y);
            OutS[c * OPITCH + row1] = fmaf(THITA, O[nb][2] * inv1, nv1.x);
            OutS[(c + 1) * OPITCH + row1] = fmaf(THITA, O[nb][3] * inv1, nv1.y);
        }
    }
    __syncthreads();
    {
        float* ob = out + (size_t)b * CH * NSEQ + q0;
        for (int i = tid; i < 128 * 128 / 4; i += 256) {
            int idx = i * 4;
            int c = idx >> 7, nl = idx & 127;
            float4 v = *(const float4*)(OutS + c * OPITCH + nl);
            *(float4*)(ob + (size_t)c * NSEQ + nl) = v;
        }
    }
}

// ---------------- host launch --------------------------------------------------
extern "C" void kernel_launch(void* const* d_in, const int* in_sizes, int n_in,
                              void* d_out, int out_size) {
    const float* event = (const float*)d_in[0];
    const float* W[12];
    const float* Bv[12];
    for (int i = 0; i < 12; i++) {
        W[i] = (const float*)d_in[1 + 2 * i];
        Bv[i] = (const float*)d_in[2 + 2 * i];
    }

    float *nowval, *bc1, *bc2;
    bf16 *qb, *kb, *vb;
    bf16 *wb1, *wb2, *wbt, *wbnk, *wbq, *wbk, *wbv, *w8hi, *w8lo;
    cudaGetSymbolAddress((void**)&nowval, g_nowval);
    cudaGetSymbolAddress((void**)&qb, g_qb);
    cudaGetSymbolAddress((void**)&kb, g_kb);
    cudaGetSymbolAddress((void**)&vb, g_vb);
    cudaGetSymbolAddress((void**)&wb1, g_wb1);
    cudaGetSymbolAddress((void**)&wb2, g_wb2);
    cudaGetSymbolAddress((void**)&wbt, g_wbt);
    cudaGetSymbolAddress((void**)&wbnk, g_wbnk);
    cudaGetSymbolAddress((void**)&wbq, g_wbq);
    cudaGetSymbolAddress((void**)&wbk, g_wbk);
    cudaGetSymbolAddress((void**)&wbv, g_wbv);
    cudaGetSymbolAddress((void**)&w8hi, g_w8hi);
    cudaGetSymbolAddress((void**)&w8lo, g_w8lo);
    cudaGetSymbolAddress((void**)&bc1, g_bc1);
    cudaGetSymbolAddress((void**)&bc2, g_bc2);

    cudaFuncSetAttribute(attn_kernel, cudaFuncAttributeMaxDynamicSharedMemorySize, ATTN_SMEM);
    cudaFuncSetAttribute(fused_conv_kernel, cudaFuncAttributeMaxDynamicSharedMemorySize, FUSED_SMEM);

    prep_w_kernel<<<640, 256>>>(W[1], W[3], W[2], W[4], W[5], W[7], W[9], W[10], W[11], W[8],
                                Bv[1], Bv[3], Bv[2], Bv[4]);

    fused_conv_kernel<<<PIX / 128, 256, FUSED_SMEM>>>(
        event, W[0], Bv[0], W[6], Bv[6],
        wb1, bc1, wb2, bc2, wbt, Bv[5], wbnk, Bv[7],
        wbq, Bv[9], wbk, Bv[10], wbv, Bv[11],
        w8hi, w8lo, Bv[8],
        qb, kb, vb, nowval);

    attn_kernel<<<dim3(NSEQ / 128, BSZ), 256, ATTN_SMEM>>>(qb, kb, vb, nowval, 128,
                                                           (float*)d_out);
}

// round 15
// speedup vs baseline: 1.0399x; 1.0012x over previous
#include <cuda_runtime.h>
#include <cuda_bf16.h>
#include <cstdint>

// Problem constants
#define PIX 16384        // B*H*W
#define NSEQ 4096        // H*W
#define BSZ 4
#define CH 128
#define THITA 1e-4f

typedef __nv_bfloat16 bf16;

// ---------------- scratch (device globals; no allocation allowed) -------------
__device__ float g_nowval[PIX * 128];
__device__ bf16 g_qb[PIX * 128];
__device__ bf16 g_kb[PIX * 128];
__device__ bf16 g_vb[PIX * 128];
// bf16 weights
__device__ bf16 g_wb1[256 * 128];   // [w_pro_key ; w_lat_key]
__device__ bf16 g_wb2[256 * 128];   // [w_pro_val ; w_lat_val]
__device__ bf16 g_wbt[128 * 256];   // w_tmp1
__device__ bf16 g_wbnk[128 * 128];  // w_now_key
__device__ bf16 g_wbq[128 * 128];
__device__ bf16 g_wbk[128 * 128];
__device__ bf16 g_wbv[128 * 128];
__device__ bf16 g_w8hi[128 * 128];  // w_now_val split hi
__device__ bf16 g_w8lo[128 * 128];  // w_now_val split lo
__device__ float g_bc1[256];
__device__ float g_bc2[256];

// ---------------- weight prep ---------------------------------------------------
__global__ void __launch_bounds__(256) prep_w_kernel(
    const float* __restrict__ wpk, const float* __restrict__ wlk,
    const float* __restrict__ wpv, const float* __restrict__ wlv,
    const float* __restrict__ wt,  const float* __restrict__ wnk,
    const float* __restrict__ wq,  const float* __restrict__ wk,
    const float* __restrict__ wv,  const float* __restrict__ wnv,
    const float* __restrict__ bpk, const float* __restrict__ blk,
    const float* __restrict__ bpv, const float* __restrict__ blv) {
    int i = blockIdx.x * blockDim.x + threadIdx.x;   // 0..163839
    if (i < 32768) {
        g_wb1[i] = __float2bfloat16(i < 16384 ? wpk[i] : wlk[i - 16384]);
        g_wb2[i] = __float2bfloat16(i < 16384 ? wpv[i] : wlv[i - 16384]);
        g_wbt[i] = __float2bfloat16(wt[i]);
    } else if (i < 49152) {
        int j = i - 32768;
        if (j < 16384) {
            g_wbnk[j] = __float2bfloat16(wnk[j]);
            float v = wnv[j];
            bf16 h = __float2bfloat16(v);
            g_w8hi[j] = h;
            g_w8lo[j] = __float2bfloat16(v - __bfloat162float(h));
        }
    } else if (i < 65536) {
        int j = i - 49152;
        g_wbq[j] = __float2bfloat16(wq[j]);
        g_wbk[j] = __float2bfloat16(wk[j]);
        g_wbv[j] = __float2bfloat16(wv[j]);
    }
    if (i < 256) {
        g_bc1[i] = i < 128 ? bpk[i] : blk[i - 128];
        g_bc2[i] = i < 128 ? bpv[i] : blv[i - 128];
    }
}

// ---------------- mma / ldmatrix helpers --------------------------------------
__device__ __forceinline__ void mma16816(float* c, const uint32_t* a, const uint32_t* b) {
    asm volatile(
        "mma.sync.aligned.m16n8k16.row.col.f32.bf16.bf16.f32 "
        "{%0,%1,%2,%3}, {%4,%5,%6,%7}, {%8,%9}, {%0,%1,%2,%3};"
        : "+f"(c[0]), "+f"(c[1]), "+f"(c[2]), "+f"(c[3])
        : "r"(a[0]), "r"(a[1]), "r"(a[2]), "r"(a[3]), "r"(b[0]), "r"(b[1]));
}

__device__ __forceinline__ void ldsm4(uint32_t& r0, uint32_t& r1, uint32_t& r2, uint32_t& r3,
                                      const void* p) {
    uint32_t addr = (uint32_t)__cvta_generic_to_shared(p);
    asm volatile("ldmatrix.sync.aligned.m8n8.x4.shared.b16 {%0,%1,%2,%3}, [%4];"
                 : "=r"(r0), "=r"(r1), "=r"(r2), "=r"(r3) : "r"(addr));
}

__device__ __forceinline__ void ldsm4t(uint32_t& r0, uint32_t& r1, uint32_t& r2, uint32_t& r3,
                                       const void* p) {
    uint32_t addr = (uint32_t)__cvta_generic_to_shared(p);
    asm volatile("ldmatrix.sync.aligned.m8n8.x4.trans.shared.b16 {%0,%1,%2,%3}, [%4];"
                 : "=r"(r0), "=r"(r1), "=r"(r2), "=r"(r3) : "r"(addr));
}

__device__ __forceinline__ uint32_t packbf2(float lo, float hi) {
    uint32_t d;
    asm("cvt.rn.bf16x2.f32 %0, %1, %2;" : "=r"(d) : "f"(hi), "f"(lo));
    return d;
}

__device__ __forceinline__ void cpasync16(void* dst, const void* src) {
    uint32_t d = (uint32_t)__cvta_generic_to_shared(dst);
    asm volatile("cp.async.cg.shared.global [%0], [%1], 16;" :: "r"(d), "l"(src));
}
#define CP_COMMIT() asm volatile("cp.async.commit_group;")
#define CP_WAIT0()  asm volatile("cp.async.wait_group 0;")
#define CP_WAIT1()  asm volatile("cp.async.wait_group 1;")

// ============ fused conv chain (W double-buffered) =============================
// preW/preBuf: prefetch the NEXT stage's 32KB W during this stage's MMA.
// preW2a/b: prefetch 2x32KB (w8hi/w8lo) into preBuf2 / preBuf2+16384 elems.
template <int K>
__device__ __forceinline__ void stage_gemm(
    const bf16* __restrict__ inb,
    const bf16* __restrict__ wg,
    const float* __restrict__ bias,
    bf16* __restrict__ wbuf,
    bf16* __restrict__ outb,
    bf16* __restrict__ outg,
    int m0, int tid,
    const bf16* __restrict__ preW, bf16* __restrict__ preBuf, bool preloaded,
    const bf16* __restrict__ preW2a = nullptr, const bf16* __restrict__ preW2b = nullptr,
    bf16* __restrict__ preBuf2 = nullptr) {
    const int lane = tid & 31, wid = tid >> 5;
    const int wm = (wid & 1) * 64, wn = (wid >> 1) * 32;
    const int g = lane >> 2, tc = lane & 3;
    const int rA_loc = ((lane >> 3) & 1) * 8 + (lane & 7);
    const int cA_bit = (lane >> 4) & 1;
    const int rB_loc = ((lane >> 4) & 1) * 8 + (lane & 7);
    const int cB_bit = (lane >> 3) & 1;
    constexpr int CPR = K >> 3;

    if (!preloaded) {
#pragma unroll
        for (int i = tid; i < 128 * CPR; i += 256) {
            int n = i / CPR, ck = i % CPR;
            int kb = ck >> 3, c8 = ck & 7;
            cpasync16((uint4*)wbuf + kb * 1024 + n * 8 + (c8 ^ (n & 7)),
                      (const uint4*)wg + i);
        }
        CP_COMMIT();
    }
    CP_WAIT0();
    __syncthreads();

    // prefetch next stage's W (K=128 layout) and/or nowval B operands
    if (preW) {
#pragma unroll
        for (int i = tid; i < 2048; i += 256) {
            int n = i >> 4, ck = i & 15;
            int kb = ck >> 3, c8 = ck & 7;
            cpasync16((uint4*)preBuf + kb * 1024 + n * 8 + (c8 ^ (n & 7)),
                      (const uint4*)preW + i);
        }
        CP_COMMIT();
    }
    if (preW2a) {
#pragma unroll
        for (int i = tid; i < 2048; i += 256) {
            int n = i >> 4, ck = i & 15;
            int kb = ck >> 3, c8 = ck & 7;
            int sidx = kb * 1024 + n * 8 + (c8 ^ (n & 7));
            cpasync16((uint4*)preBuf2 + sidx, (const uint4*)preW2a + i);
            cpasync16((uint4*)(preBuf2 + 16384) + sidx, (const uint4*)preW2b + i);
        }
        CP_COMMIT();
    }

    float acc[4][4][4];
#pragma unroll
    for (int i = 0; i < 4; i++)
#pragma unroll
        for (int j = 0; j < 4; j++)
#pragma unroll
            for (int l = 0; l < 4; l++) acc[i][j][l] = 0.f;

#pragma unroll
    for (int kb = 0; kb < K / 64; kb++) {
        const bf16* As = inb + kb * 8192;
        const bf16* Bs = wbuf + kb * 8192;
#pragma unroll
        for (int ks = 0; ks < 4; ks++) {
            uint32_t a[4][4], bf[2][4];
#pragma unroll
            for (int mi = 0; mi < 4; mi++) {
                int r = wm + mi * 16 + rA_loc;
                int ch = 2 * ks + cA_bit;
                ldsm4(a[mi][0], a[mi][1], a[mi][2], a[mi][3],
                      As + r * 64 + ((ch ^ (r & 7)) << 3));
            }
#pragma unroll
            for (int ni = 0; ni < 2; ni++) {
                int r = wn + ni * 16 + rB_loc;
                int ch = 2 * ks + cB_bit;
                ldsm4(bf[ni][0], bf[ni][1], bf[ni][2], bf[ni][3],
                      Bs + r * 64 + ((ch ^ (r & 7)) << 3));
            }
#pragma unroll
            for (int mi = 0; mi < 4; mi++)
#pragma unroll
                for (int ni = 0; ni < 2; ni++) {
                    uint32_t b0[2] = {bf[ni][0], bf[ni][1]};
                    mma16816(acc[mi][2 * ni], a[mi], b0);
                    uint32_t b1[2] = {bf[ni][2], bf[ni][3]};
                    mma16816(acc[mi][2 * ni + 1], a[mi], b1);
                }
        }
    }

#pragma unroll
    for (int mi = 0; mi < 4; mi++) {
        int r0 = wm + mi * 16 + g;
#pragma unroll
        for (int n8 = 0; n8 < 4; n8++) {
            int c = wn + n8 * 8 + 2 * tc;
            float2 bv = *(const float2*)(bias + c);
            uint32_t p0 = packbf2(fmaxf(acc[mi][n8][0] + bv.x, 0.f),
                                  fmaxf(acc[mi][n8][1] + bv.y, 0.f));
            uint32_t p1 = packbf2(fmaxf(acc[mi][n8][2] + bv.x, 0.f),
                                  fmaxf(acc[mi][n8][3] + bv.y, 0.f));
            if (outb) {
                int kb_o = c >> 6, cl = c & 63, chk = cl >> 3, off = cl & 7;
                bf16* base = outb + kb_o * 8192;
                *(uint32_t*)(base + r0 * 64 + ((chk ^ (r0 & 7)) << 3) + off) = p0;
                int r1 = r0 + 8;
                *(uint32_t*)(base + r1 * 64 + ((chk ^ (r1 & 7)) << 3) + off) = p1;
            } else {
                *(uint32_t*)(outg + (size_t)(m0 + r0) * 128 + c) = p0;
                *(uint32_t*)(outg + (size_t)(m0 + r0 + 8) * 128 + c) = p1;
            }
        }
    }
    __syncthreads();
}

#define FUSED_SMEM (65536 + 65536 + 32768 + 65536)   // A,B,C,W = 229376 B

__global__ void __launch_bounds__(256, 1) fused_conv_kernel(
    const float* __restrict__ event,
    const float* __restrict__ w0, const float* __restrict__ b0,
    const float* __restrict__ w6, const float* __restrict__ b6,
    const bf16* __restrict__ wb1, const float* __restrict__ bc1,
    const bf16* __restrict__ wb2, const float* __restrict__ bc2,
    const bf16* __restrict__ wbt, const float* __restrict__ bt,
    const bf16* __restrict__ wbnk, const float* __restrict__ bnk,
    const bf16* __restrict__ wbq, const float* __restrict__ bq,
    const bf16* __restrict__ wbk, const float* __restrict__ bk,
    const bf16* __restrict__ wbv, const float* __restrict__ bv,
    const bf16* __restrict__ w8hi, const bf16* __restrict__ w8lo,
    const float* __restrict__ b8,
    bf16* __restrict__ qb, bf16* __restrict__ kb_, bf16* __restrict__ vb,
    float* __restrict__ nowval) {
    extern __shared__ char sm[];
    bf16* A = (bf16*)sm;
    bf16* B = (bf16*)(sm + 65536);
    bf16* C = (bf16*)(sm + 131072);
    bf16* W0 = (bf16*)(sm + 163840);
    bf16* W1 = W0 + 16384;              // second 32KB of W region
    const int tid = threadIdx.x, lane = tid & 31, wid = tid >> 5;
    const int m0 = blockIdx.x * 128;
    const float* ev = event + (size_t)(m0 >> 12) * 6 * NSEQ + (m0 & 4095);

    // ---- neigh (K=4 conv) -> A, 256 ch ----
    for (int i = tid; i < 4096; i += 256) {
        int r = i >> 5, ck = i & 31;
        float x0 = ev[r], x1 = ev[NSEQ + r], x2 = ev[4 * NSEQ + r], x3 = ev[5 * NSEQ + r];
        uint32_t pk[4];
#pragma unroll
        for (int j = 0; j < 4; j++) {
            int c0 = ck * 8 + 2 * j, c1 = c0 + 1;
            float v0 = fmaf(w0[c0 * 4 + 3], x3, fmaf(w0[c0 * 4 + 2], x2,
                       fmaf(w0[c0 * 4 + 1], x1, fmaf(w0[c0 * 4], x0, b0[c0]))));
            float v1 = fmaf(w0[c1 * 4 + 3], x3, fmaf(w0[c1 * 4 + 2], x2,
                       fmaf(w0[c1 * 4 + 1], x1, fmaf(w0[c1 * 4], x0, b0[c1]))));
            pk[j] = packbf2(fmaxf(v0, 0.f), fmaxf(v1, 0.f));
        }
        ((uint4*)A)[(ck >> 3) * 1024 + r * 8 + ((ck & 7) ^ (r & 7))] =
            make_uint4(pk[0], pk[1], pk[2], pk[3]);
    }
    __syncthreads();

    // key path
    stage_gemm<128>(A, wb1, bc1, W0, B, nullptr, m0, tid, wb1 + 16384, W1, false);
    stage_gemm<128>(A, wb1 + 16384, bc1 + 128, W1, B + 2 * 8192, nullptr, m0, tid,
                    nullptr, nullptr, true);
    stage_gemm<256>(B, wbt, bt, W0, C, nullptr, m0, tid, nullptr, nullptr, false);
    stage_gemm<128>(C, wbq, bq, W0, nullptr, qb, m0, tid, wb2, W1, false);

    // val path
    stage_gemm<128>(A + 2 * 8192, wb2, bc2, W1, B, nullptr, m0, tid, wb2 + 16384, W0, true);
    stage_gemm<128>(A + 2 * 8192, wb2 + 16384, bc2 + 128, W0, B + 2 * 8192, nullptr, m0, tid,
                    nullptr, nullptr, true);
    stage_gemm<256>(B, wbt, bt, W0, C, nullptr, m0, tid, nullptr, nullptr, false);
    stage_gemm<128>(C, wbv, bv, W0, nullptr, vb, m0, tid, wbnk, W1, false);

    // ---- nowf (K=2 conv) -> A kb0-1 (bf16) ----
    for (int i = tid; i < 2048; i += 256) {
        int r = i >> 4, ck = i & 15;
        float x = ev[2 * NSEQ + r], y = ev[3 * NSEQ + r];
        uint32_t pk[4];
#pragma unroll
        for (int j = 0; j < 4; j++) {
            int c0 = ck * 8 + 2 * j, c1 = c0 + 1;
            float v0 = fmaxf(fmaf(w6[c0 * 2 + 1], y, fmaf(w6[c0 * 2], x, b6[c0])), 0.f);
            float v1 = fmaxf(fmaf(w6[c1 * 2 + 1], y, fmaf(w6[c1 * 2], x, b6[c1])), 0.f);
            pk[j] = packbf2(v0, v1);
        }
        ((uint4*)A)[(ck >> 3) * 1024 + r * 8 + ((ck & 7) ^ (r & 7))] =
            make_uint4(pk[0], pk[1], pk[2], pk[3]);
    }
    __syncthreads();
    stage_gemm<128>(A, wbnk, bnk, W1, C, nullptr, m0, tid, wbk, W0, true);
    // s10: also prefetch w8hi/w8lo into A (free: s9 done reading it)
    stage_gemm<128>(C, wbk, bk, W0, nullptr, kb_, m0, tid, nullptr, nullptr, true,
                    w8hi, w8lo, A);

    // ================= nowval phase ==========================================
    // Bh/Bl resident in A (prefetched during s10); Ah/Al per-k0 in C; aux in B.
    {
        bf16* Bh = A;                      // 2 subtiles (32KB)
        bf16* Bl = A + 16384;              // 2 subtiles (32KB)
        bf16* Ah = C;                      // 1 subtile per k0 (16KB)
        bf16* Al = C + 8192;               // 1 subtile per k0 (16KB)
        float* x2s = (float*)B;            // [128][2]
        float* w6s = x2s + 256;            // [128][2]
        float* b6s = w6s + 256;            // [128]

        const int wm = (wid & 1) * 64, wn = (wid >> 1) * 32;
        const int g = lane >> 2, tc = lane & 3;
        const int rA_loc = ((lane >> 3) & 1) * 8 + (lane & 7);
        const int cA_bit = (lane >> 4) & 1;
        const int rB_loc = ((lane >> 4) & 1) * 8 + (lane & 7);
        const int cB_bit = (lane >> 3) & 1;

        if (tid < 128) {
            x2s[2 * tid] = ev[2 * NSEQ + tid];
            x2s[2 * tid + 1] = ev[3 * NSEQ + tid];
            b6s[tid] = b6[tid];
        } else {
            int j = tid - 128;
            ((float2*)w6s)[j] = ((const float2*)w6)[j];
        }
        CP_WAIT0();          // Bh/Bl staged
        __syncthreads();

        float acc[4][4][4];
#pragma unroll
        for (int i = 0; i < 4; i++)
#pragma unroll
            for (int j = 0; j < 4; j++)
#pragma unroll
                for (int l = 0; l < 4; l++) acc[i][j][l] = 0.f;

        for (int k0 = 0; k0 < 128; k0 += 64) {
#pragma unroll
            for (int i = 0; i < 4; i++) {
                int li = tid + i * 256;
                int r = li >> 3, cch = li & 7;
                float x0 = x2s[2 * r], x1 = x2s[2 * r + 1];
                uint4 hq, lq;
                bf16* hp = (bf16*)&hq;
                bf16* lp = (bf16*)&lq;
#pragma unroll
                for (int j = 0; j < 8; j++) {
                    int k = k0 + cch * 8 + j;
                    float v = fmaxf(fmaf(w6s[2 * k + 1], x1, fmaf(w6s[2 * k], x0, b6s[k])), 0.f);
                    bf16 h = __float2bfloat16(v);
                    hp[j] = h;
                    lp[j] = __float2bfloat16(v - __bfloat162float(h));
                }
                int sidx = r * 8 + (cch ^ (r & 7));
                ((uint4*)Ah)[sidx] = hq;
                ((uint4*)Al)[sidx] = lq;
            }
            __syncthreads();
            const bf16* Bhk = Bh + (k0 >> 6) * 8192;
            const bf16* Blk = Bl + (k0 >> 6) * 8192;
#pragma unroll
            for (int ks = 0; ks < 4; ks++) {
                uint32_t ah[4][4], al[4][4], bh[2][4], bl[2][4];
#pragma unroll
                for (int mi = 0; mi < 4; mi++) {
                    int r = wm + mi * 16 + rA_loc;
                    int ch = 2 * ks + cA_bit;
                    int off = r * 64 + ((ch ^ (r & 7)) << 3);
                    ldsm4(ah[mi][0], ah[mi][1], ah[mi][2], ah[mi][3], Ah + off);
                    ldsm4(al[mi][0], al[mi][1], al[mi][2], al[mi][3], Al + off);
                }
#pragma unroll
                for (int ni = 0; ni < 2; ni++) {
                    int r = wn + ni * 16 + rB_loc;
                    int ch = 2 * ks + cB_bit;
                    int off = r * 64 + ((ch ^ (r & 7)) << 3);
                    ldsm4(bh[ni][0], bh[ni][1], bh[ni][2], bh[ni][3], Bhk + off);
                    ldsm4(bl[ni][0], bl[ni][1], bl[ni][2], bl[ni][3], Blk + off);
                }
#pragma unroll
                for (int mi = 0; mi < 4; mi++)
#pragma unroll
                    for (int ni = 0; ni < 2; ni++) {
                        uint32_t h0[2] = {bh[ni][0], bh[ni][1]};
                        uint32_t h1[2] = {bh[ni][2], bh[ni][3]};
                        uint32_t l0[2] = {bl[ni][0], bl[ni][1]};
                        uint32_t l1[2] = {bl[ni][2], bl[ni][3]};
                        mma16816(acc[mi][2 * ni], ah[mi], h0);
                        mma16816(acc[mi][2 * ni + 1], ah[mi], h1);
                        mma16816(acc[mi][2 * ni], ah[mi], l0);
                        mma16816(acc[mi][2 * ni + 1], ah[mi], l1);
                        mma16816(acc[mi][2 * ni], al[mi], h0);
                        mma16816(acc[mi][2 * ni + 1], al[mi], h1);
                    }
            }
            __syncthreads();
        }
#pragma unroll
        for (int mi = 0; mi < 4; mi++) {
            int r0 = m0 + wm + mi * 16 + g;
#pragma unroll
            for (int n8 = 0; n8 < 4; n8++) {
                int c = wn + n8 * 8 + 2 * tc;
                float2 bv = *(const float2*)(b8 + c);
                float2 v01, v23;
                v01.x = fmaxf(acc[mi][n8][0] + bv.x, 0.f);
                v01.y = fmaxf(acc[mi][n8][1] + bv.y, 0.f);
                v23.x = fmaxf(acc[mi][n8][2] + bv.x, 0.f);
                v23.y = fmaxf(acc[mi][n8][3] + bv.y, 0.f);
                *(float2*)(nowval + (size_t)r0 * 128 + c) = v01;
                *(float2*)(nowval + (size_t)(r0 + 8) * 128 + c) = v23;
            }
        }
    }
}

// ---------------- fast exp (Schraudolph); clamp low side ----------------------
__device__ __forceinline__ float fast_exp(float x) {
    x = fmaxf(x, -80.f);
    int i = (int)(fmaf(x, 12102203.0f, 1064866805.0f));
    return __int_as_float(i);
}

// ---- flash attention, bf16 HMMA, BM=128 BN=128, lagged softmax (round-11) ----
#define OPITCH 132
#define ATTN_SMEM 131072   // 2 stages * (32KB K + 32KB V)

__global__ void __launch_bounds__(256, 1) attn_kernel(
    const bf16* __restrict__ gq,
    const bf16* __restrict__ gk,
    const bf16* __restrict__ gv,
    const float* __restrict__ gnv, int nv_ld,
    float* __restrict__ out) {
    extern __shared__ char smraw[];
    float* OutS = (float*)smraw;                   // reused post-loop, [128][OPITCH]

    const int tid = threadIdx.x;
    const int lane = tid & 31, w = tid >> 5;
    const int g = lane >> 2, tc = lane & 3;
    const int b = blockIdx.y;
    const int q0 = blockIdx.x * 128;

    uint32_t qa[8][4];
    {
        const bf16* Qb = gq + ((size_t)(b * NSEQ) + q0 + w * 16) * CH;
#pragma unroll
        for (int kb = 0; kb < 8; kb++) {
            qa[kb][0] = *(const uint32_t*)(Qb + (size_t)g * CH + kb * 16 + 2 * tc);
            qa[kb][1] = *(const uint32_t*)(Qb + (size_t)(g + 8) * CH + kb * 16 + 2 * tc);
            qa[kb][2] = *(const uint32_t*)(Qb + (size_t)g * CH + kb * 16 + 8 + 2 * tc);
            qa[kb][3] = *(const uint32_t*)(Qb + (size_t)(g + 8) * CH + kb * 16 + 8 + 2 * tc);
        }
    }

    float O[16][4];
#pragma unroll
    for (int i = 0; i < 16; i++)
#pragma unroll
        for (int j = 0; j < 4; j++) O[i][j] = 0.f;
    float m0s = 0.f, m1s = 0.f;
    float lrow0 = 0.f, lrow1 = 0.f;

    const int rK_loc = ((lane >> 4) & 1) * 8 + (lane & 7);
    const int cK_bit = (lane >> 3) & 1;
    const int rV_loc = ((lane >> 3) & 1) * 8 + (lane & 7);
    const int cV_bit = lane >> 4;

    const bf16* Kgb = gk + (size_t)b * NSEQ * CH;
    const bf16* Vgb = gv + (size_t)b * NSEQ * CH;

    auto stage = [&](int jt, int s) {
        const uint4* Kg = (const uint4*)(Kgb + (size_t)jt * 128 * CH);
        const uint4* Vg = (const uint4*)(Vgb + (size_t)jt * 128 * CH);
        uint4* Kd = (uint4*)(smraw + s * 65536);
        uint4* Vd = Kd + 2048;
#pragma unroll
        for (int i = tid; i < 2048; i += 256) {
            int r = i >> 4, ch = i & 15, sch = ch ^ (r & 7);
            cpasync16(Kd + r * 16 + sch, Kg + i);
            cpasync16(Vd + r * 16 + sch, Vg + i);
        }
    };

    stage(0, 0);
    CP_COMMIT();

    for (int jt = 0; jt < NSEQ / 128; jt++) {
        if (jt + 1 < NSEQ / 128) stage(jt + 1, (jt + 1) & 1);
        CP_COMMIT();
        CP_WAIT1();
        __syncthreads();

        bf16* Ks = (bf16*)(smraw + (jt & 1) * 65536);
        bf16* Vs = Ks + 128 * 128;

        float S[16][4];
#pragma unroll
        for (int i = 0; i < 16; i++)
#pragma unroll
            for (int j = 0; j < 4; j++) S[i][j] = 0.f;
#pragma unroll
        for (int kb = 0; kb < 8; kb++) {
#pragma unroll
            for (int p = 0; p < 8; p++) {
                int r = p * 16 + rK_loc;
                int ch = 2 * kb + cK_bit;
                uint32_t b0, b1, b2, b3;
                ldsm4(b0, b1, b2, b3, Ks + r * 128 + ((ch ^ (r & 7)) << 3));
                uint32_t bb[2] = {b0, b1};
                mma16816(S[2 * p], qa[kb], bb);
                uint32_t bb2[2] = {b2, b3};
                mma16816(S[2 * p + 1], qa[kb], bb2);
            }
        }

        float t0 = -1e30f, t1 = -1e30f;
#pragma unroll
        for (int nb = 0; nb < 16; nb++) {
            t0 = fmaxf(t0, fmaxf(S[nb][0], S[nb][1]));
            t1 = fmaxf(t1, fmaxf(S[nb][2], S[nb][3]));
        }
        if (jt == 0) {
            float u0 = fmaxf(t0, __shfl_xor_sync(0xffffffffu, t0, 1));
            u0 = fmaxf(u0, __shfl_xor_sync(0xffffffffu, u0, 2));
            float u1 = fmaxf(t1, __shfl_xor_sync(0xffffffffu, t1, 1));
            u1 = fmaxf(u1, __shfl_xor_sync(0xffffffffu, u1, 2));
            m0s = u0 + 4.f;
            m1s = u1 + 4.f;
        }

#pragma unroll
        for (int nb = 0; nb < 16; nb++) {
            S[nb][0] = fast_exp(S[nb][0] - m0s);
            S[nb][1] = fast_exp(S[nb][1] - m0s);
            S[nb][2] = fast_exp(S[nb][2] - m1s);
            S[nb][3] = fast_exp(S[nb][3] - m1s);
            lrow0 += S[nb][0] + S[nb][1];
            lrow1 += S[nb][2] + S[nb][3];
        }

        uint32_t pa[8][4];
#pragma unroll
        for (int jb = 0; jb < 8; jb++) {
            pa[jb][0] = packbf2(S[2 * jb][0], S[2 * jb][1]);
            pa[jb][1] = packbf2(S[2 * jb][2], S[2 * jb][3]);
            pa[jb][2] = packbf2(S[2 * jb + 1][0], S[2 * jb + 1][1]);
            pa[jb][3] = packbf2(S[2 * jb + 1][2], S[2 * jb + 1][3]);
        }

#pragma unroll
        for (int jb = 0; jb < 8; jb++) {
            int r = jb * 16 + rV_loc;
#pragma unroll
            for (int cp = 0; cp < 8; cp++) {
                int ch = 2 * cp + cV_bit;
                uint32_t b0, b1, b2, b3;
                ldsm4t(b0, b1, b2, b3, Vs + r * 128 + ((ch ^ (r & 7)) << 3));
                uint32_t bb[2] = {b0, b1};
                mma16816(O[2 * cp], pa[jb], bb);
                uint32_t bb2[2] = {b2, b3};
                mma16816(O[2 * cp + 1], pa[jb], bb2);
            }
        }

        if (jt > 0 && jt + 1 < NSEQ / 128) {
            float u0 = fmaxf(t0, __shfl_xor_sync(0xffffffffu, t0, 1));
            u0 = fmaxf(u0, __shfl_xor_sync(0xffffffffu, u0, 2));
            float u1 = fmaxf(t1, __shfl_xor_sync(0xffffffffu, t1, 1));
            u1 = fmaxf(u1, __shfl_xor_sync(0xffffffffu, u1, 2));
            bool inc = (u0 > m0s) | (u1 > m1s);
            if (__any_sync(0xffffffffu, inc)) {
                float nm0 = u0 > m0s ? u0 + 4.f : m0s;
                float nm1 = u1 > m1s ? u1 + 4.f : m1s;
                float scl0 = fast_exp(m0s - nm0), scl1 = fast_exp(m1s - nm1);
                lrow0 *= scl0; lrow1 *= scl1;
#pragma unroll
                for (int nb = 0; nb < 16; nb++) {
                    O[nb][0] *= scl0; O[nb][1] *= scl0;
                    O[nb][2] *= scl1; O[nb][3] *= scl1;
                }
                m0s = nm0; m1s = nm1;
            }
        }
        __syncthreads();
    }

    lrow0 += __shfl_xor_sync(0xffffffffu, lrow0, 1);
    lrow0 += __shfl_xor_sync(0xffffffffu, lrow0, 2);
    lrow1 += __shfl_xor_sync(0xffffffffu, lrow1, 1);
    lrow1 += __shfl_xor_sync(0xffffffffu, lrow1, 2);

    {
        float inv0 = 1.f / lrow0, inv1 = 1.f / lrow1;
        int row0 = w * 16 + g, row1 = row0 + 8;
        const float* nvp0 = gnv + ((size_t)(b * NSEQ) + q0 + row0) * nv_ld;
        const float* nvp1 = gnv + ((size_t)(b * NSEQ) + q0 + row1) * nv_ld;
#pragma unroll
        for (int nb = 0; nb < 16; nb++) {
            int c = nb * 8 + 2 * tc;
            float2 nv0 = *(const float2*)(nvp0 + c);
            float2 nv1 = *(const float2*)(nvp1 + c);
            OutS[c * OPITCH + row0] = fmaf(THITA, O[nb][0] * inv0, nv0.x);
            OutS[(c + 1) * OPITCH + row0] = fmaf(THITA, O[nb][1] * inv0, nv0.y);
            OutS[c * OPITCH + row1] = fmaf(THITA, O[nb][2] * inv1, nv1.x);
            OutS[(c + 1) * OPITCH + row1] = fmaf(THITA, O[nb][3] * inv1, nv1.y);
        }
    }
    __syncthreads();
    {
        float* ob = out + (size_t)b * CH * NSEQ + q0;
        for (int i = tid; i < 128 * 128 / 4; i += 256) {
            int idx = i * 4;
            int c = idx >> 7, nl = idx & 127;
            float4 v = *(const float4*)(OutS + c * OPITCH + nl);
            *(float4*)(ob + (size_t)c * NSEQ + nl) = v;
        }
    }
}

// ---------------- host launch --------------------------------------------------
extern "C" void kernel_launch(void* const* d_in, const int* in_sizes, int n_in,
                              void* d_out, int out_size) {
    const float* event = (const float*)d_in[0];
    const float* W[12];
    const float* Bv[12];
    for (int i = 0; i < 12; i++) {
        W[i] = (const float*)d_in[1 + 2 * i];
        Bv[i] = (const float*)d_in[2 + 2 * i];
    }

    float *nowval, *bc1, *bc2;
    bf16 *qb, *kb, *vb;
    bf16 *wb1, *wb2, *wbt, *wbnk, *wbq, *wbk, *wbv, *w8hi, *w8lo;
    cudaGetSymbolAddress((void**)&nowval, g_nowval);
    cudaGetSymbolAddress((void**)&qb, g_qb);
    cudaGetSymbolAddress((void**)&kb, g_kb);
    cudaGetSymbolAddress((void**)&vb, g_vb);
    cudaGetSymbolAddress((void**)&wb1, g_wb1);
    cudaGetSymbolAddress((void**)&wb2, g_wb2);
    cudaGetSymbolAddress((void**)&wbt, g_wbt);
    cudaGetSymbolAddress((void**)&wbnk, g_wbnk);
    cudaGetSymbolAddress((void**)&wbq, g_wbq);
    cudaGetSymbolAddress((void**)&wbk, g_wbk);
    cudaGetSymbolAddress((void**)&wbv, g_wbv);
    cudaGetSymbolAddress((void**)&w8hi, g_w8hi);
    cudaGetSymbolAddress((void**)&w8lo, g_w8lo);
    cudaGetSymbolAddress((void**)&bc1, g_bc1);
    cudaGetSymbolAddress((void**)&bc2, g_bc2);

    cudaFuncSetAttribute(attn_kernel, cudaFuncAttributeMaxDynamicSharedMemorySize, ATTN_SMEM);
    cudaFuncSetAttribute(fused_conv_kernel, cudaFuncAttributeMaxDynamicSharedMemorySize, FUSED_SMEM);

    prep_w_kernel<<<640, 256>>>(W[1], W[3], W[2], W[4], W[5], W[7], W[9], W[10], W[11], W[8],
                                Bv[1], Bv[3], Bv[2], Bv[4]);

    fused_conv_kernel<<<PIX / 128, 256, FUSED_SMEM>>>(
        event, W[0], Bv[0], W[6], Bv[6],
        wb1, bc1, wb2, bc2, wbt, Bv[5], wbnk, Bv[7],
        wbq, Bv[9], wbk, Bv[10], wbv, Bv[11],
        w8hi, w8lo, Bv[8],
        qb, kb, vb, nowval);

    attn_kernel<<<dim3(NSEQ / 128, BSZ), 256, ATTN_SMEM>>>(qb, kb, vb, nowval, 128,
                                                           (float*)d_out);
}